// round 1
// baseline (speedup 1.0000x reference)
#include <cuda_runtime.h>
#include <cstdint>

#define Nn 100000
#define Ee 600000
#define HIDD 128
#define HEADSN 16
#define EPSBN 1e-5f
#define SLOPE 0.2f

// ---------------- scratch (device globals; no allocs allowed) ----------------
__device__ float g_HC[(size_t)Nn * 640];    // JumpingKnowledge buffer: 5 column blocks of 128
__device__ float g_z[(size_t)Nn * 128];     // GAT projection
__device__ float g_t[(size_t)Nn * 256];     // FF hidden / dec hidden
__device__ float g_y[(size_t)Nn * 128];     // pre-BN residual sum
__device__ float g_hmid[(size_t)Nn * 128];  // BN1 output
__device__ float g_el[(size_t)Nn * 16];
__device__ float g_er[(size_t)Nn * 16];
__device__ float g_bnsum[256];              // [0:128) sum, [128:256) sumsq
__device__ int   g_deg[Nn];
__device__ int   g_scan[Nn];
__device__ int   g_bsum[128];
__device__ int   g_rowptr[Nn + 1];
__device__ int   g_cursor[Nn];
__device__ int   g_eid[Ee];

// ---------------- CSR build ----------------
__global__ void k_count(const int* __restrict__ dst) {
    int e = blockIdx.x * blockDim.x + threadIdx.x;
    if (e < Ee) atomicAdd(&g_deg[dst[e]], 1);
}

__global__ void k_scan1() {  // block = 1024 threads, inclusive scan per chunk
    __shared__ int s[1024];
    int i = blockIdx.x * 1024 + threadIdx.x;
    int v = (i < Nn) ? g_deg[i] : 0;
    s[threadIdx.x] = v;
    __syncthreads();
    for (int off = 1; off < 1024; off <<= 1) {
        int t = (threadIdx.x >= off) ? s[threadIdx.x - off] : 0;
        __syncthreads();
        s[threadIdx.x] += t;
        __syncthreads();
    }
    if (i < Nn) g_scan[i] = s[threadIdx.x];
    if (threadIdx.x == 1023) g_bsum[blockIdx.x] = s[1023];
}

__global__ void k_scan2(int nb) {  // 1 block, 128 threads
    __shared__ int s[128];
    int v = (threadIdx.x < nb) ? g_bsum[threadIdx.x] : 0;
    s[threadIdx.x] = v;
    __syncthreads();
    for (int off = 1; off < 128; off <<= 1) {
        int t = (threadIdx.x >= off) ? s[threadIdx.x - off] : 0;
        __syncthreads();
        s[threadIdx.x] += t;
        __syncthreads();
    }
    g_bsum[threadIdx.x] = (threadIdx.x == 0) ? 0 : s[threadIdx.x - 1];
}

__global__ void k_finalize() {
    int i = blockIdx.x * blockDim.x + threadIdx.x;
    if (i >= Nn) return;
    int incl = g_scan[i] + g_bsum[i >> 10];
    g_rowptr[i + 1] = incl;
    g_cursor[i] = incl - g_deg[i];
    if (i == 0) g_rowptr[0] = 0;
}

__global__ void k_fill(const int* __restrict__ dst) {
    int e = blockIdx.x * blockDim.x + threadIdx.x;
    if (e < Ee) {
        int d = dst[e];
        int p = atomicAdd(&g_cursor[d], 1);
        g_eid[p] = e;
    }
}

// ---------------- embed MLP (+skip) ----------------
__global__ void k_embed(const float* __restrict__ x,
                        const float* __restrict__ W1, const float* __restrict__ b1,
                        const float* __restrict__ W2, const float* __restrict__ b2,
                        const float* __restrict__ Ws, const float* __restrict__ bs) {
    __shared__ float t[128];
    int n = blockIdx.x, c = threadIdx.x;
    float x0 = x[n * 2], x1 = x[n * 2 + 1];
    float tv = x0 * W1[c] + x1 * W1[128 + c] + b1[c];
    t[c] = tv > 0.f ? tv : 0.f;
    __syncthreads();
    float acc = b2[c] + x0 * Ws[c] + x1 * Ws[128 + c] + bs[c];
#pragma unroll 8
    for (int k = 0; k < 128; k++) acc += t[k] * W2[k * 128 + c];
    g_HC[(size_t)n * 640 + c] = acc;
}

// ---------------- generic fp32 SGEMM: C = A[N,M] @ B[M,K] (+bias)(relu)(+res) ----------------
template <bool RELU, bool HAS_BIAS, bool HAS_RES>
__global__ void __launch_bounds__(256) k_sgemm(
    const float* __restrict__ A, int lda,
    const float* __restrict__ B,  // row-major [M, Kcols]
    const float* __restrict__ bias,
    const float* __restrict__ Res, int ldres,
    float* __restrict__ C, int ldc,
    int Nrows, int Mred, int Kcols) {
    const int BM = 128, BN = 128, BK = 8;
    __shared__ float As[BK][BM];
    __shared__ float Bs[BK][BN];
    int tid = threadIdx.x;
    int bm = blockIdx.x * BM;
    int bn = blockIdx.y * BN;
    int ty = tid / 16, tx = tid % 16;
    int rowb = ty * 8, colb = tx * 8;
    float acc[8][8] = {};
    int arow = tid >> 1;
    int aseg = (tid & 1) * 4;
    int brow = tid >> 5;
    int bcol = (tid & 31) * 4;

    for (int kt = 0; kt < Mred; kt += BK) {
        int gr = bm + arow;
        float4 av = make_float4(0.f, 0.f, 0.f, 0.f);
        if (gr < Nrows) av = *(const float4*)(A + (size_t)gr * lda + kt + aseg);
        As[aseg + 0][arow] = av.x;
        As[aseg + 1][arow] = av.y;
        As[aseg + 2][arow] = av.z;
        As[aseg + 3][arow] = av.w;
        float4 bv = *(const float4*)(B + (size_t)(kt + brow) * Kcols + bn + bcol);
        *(float4*)&Bs[brow][bcol] = bv;
        __syncthreads();
#pragma unroll
        for (int k = 0; k < BK; k++) {
            float a[8], b[8];
            *(float4*)a = *(const float4*)&As[k][rowb];
            *(float4*)(a + 4) = *(const float4*)&As[k][rowb + 4];
            *(float4*)b = *(const float4*)&Bs[k][colb];
            *(float4*)(b + 4) = *(const float4*)&Bs[k][colb + 4];
#pragma unroll
            for (int i = 0; i < 8; i++)
#pragma unroll
                for (int j = 0; j < 8; j++) acc[i][j] += a[i] * b[j];
        }
        __syncthreads();
    }

#pragma unroll
    for (int i = 0; i < 8; i++) {
        int r = bm + rowb + i;
        if (r >= Nrows) break;
#pragma unroll
        for (int jj = 0; jj < 8; jj += 4) {
            int gc = bn + colb + jj;
            float4 v = make_float4(acc[i][jj], acc[i][jj + 1], acc[i][jj + 2], acc[i][jj + 3]);
            if (HAS_BIAS) {
                float4 bb = *(const float4*)(bias + gc);
                v.x += bb.x; v.y += bb.y; v.z += bb.z; v.w += bb.w;
            }
            if (RELU) {
                v.x = fmaxf(v.x, 0.f); v.y = fmaxf(v.y, 0.f);
                v.z = fmaxf(v.z, 0.f); v.w = fmaxf(v.w, 0.f);
            }
            if (HAS_RES) {
                float4 rr = *(const float4*)(Res + (size_t)r * ldres + gc);
                v.x += rr.x; v.y += rr.y; v.z += rr.z; v.w += rr.w;
            }
            *(float4*)(C + (size_t)r * ldc + gc) = v;
        }
    }
}

// ---------------- el / er ----------------
__global__ void k_eler(const float* __restrict__ z, const float* __restrict__ al,
                       const float* __restrict__ ar) {
    int t = blockIdx.x * blockDim.x + threadIdx.x;
    if (t >= Nn * 16) return;
    int n = t >> 4, h = t & 15;
    const float* zr = z + (size_t)n * 128 + h * 8;
    const float* a = al + h * 8;
    const float* r = ar + h * 8;
    float sl = 0.f, sr = 0.f;
#pragma unroll
    for (int d = 0; d < 8; d++) {
        float zv = zr[d];
        sl += zv * a[d];
        sr += zv * r[d];
    }
    g_el[t] = sl;
    g_er[t] = sr;
}

// ---------------- GAT aggregate (warp per node) + residual + bias -> y ----------------
__global__ void k_gat(const float* __restrict__ z, const int* __restrict__ src,
                      const float* __restrict__ hres, int ldh,
                      const float* __restrict__ bias, float* __restrict__ y) {
    int warp = (blockIdx.x * blockDim.x + threadIdx.x) >> 5;
    if (warp >= Nn) return;
    int lane = threadIdx.x & 31;
    int head = lane >> 1;  // lane covers channels [4*lane, 4*lane+4), all in head lane/2
    int beg = g_rowptr[warp], end = g_rowptr[warp + 1];
    float er_h = g_er[warp * 16 + head];

    float m = -1e30f;
    for (int i = beg; i < end; i++) {
        int s = src[g_eid[i]];
        float v = g_el[s * 16 + head] + er_h;
        v = v > 0.f ? v : SLOPE * v;
        m = fmaxf(m, v);
    }
    float den = 0.f;
    float4 acc = make_float4(0.f, 0.f, 0.f, 0.f);
    const float4* z4 = (const float4*)z;
    for (int i = beg; i < end; i++) {
        int s = src[g_eid[i]];
        float v = g_el[s * 16 + head] + er_h;
        v = v > 0.f ? v : SLOPE * v;
        float w = expf(v - m);
        den += w;
        float4 zv = z4[(size_t)s * 32 + lane];
        acc.x += w * zv.x; acc.y += w * zv.y; acc.z += w * zv.z; acc.w += w * zv.w;
    }
    float dinv = den > 0.f ? 1.f / den : 1.f;
    float4 b4 = ((const float4*)bias)[lane];
    float4 h4 = *(const float4*)(hres + (size_t)warp * ldh + lane * 4);
    float4 o;
    o.x = acc.x * dinv + b4.x + h4.x;
    o.y = acc.y * dinv + b4.y + h4.y;
    o.z = acc.z * dinv + b4.z + h4.z;
    o.w = acc.w * dinv + b4.w + h4.w;
    ((float4*)y)[(size_t)warp * 32 + lane] = o;
}

// ---------------- BatchNorm ----------------
__global__ void k_bn_stats(const float* __restrict__ y) {
    int c = threadIdx.x;
    float s = 0.f, s2 = 0.f;
    for (int n = blockIdx.x; n < Nn; n += gridDim.x) {
        float v = y[(size_t)n * 128 + c];
        s += v;
        s2 += v * v;
    }
    atomicAdd(&g_bnsum[c], s);
    atomicAdd(&g_bnsum[128 + c], s2);
}

__global__ void k_bn_apply(const float* __restrict__ y, const float* __restrict__ g,
                           const float* __restrict__ b, float* __restrict__ out, int ldo) {
    int idx = blockIdx.x * blockDim.x + threadIdx.x;
    if (idx >= Nn * 128) return;
    int n = idx >> 7, c = idx & 127;
    const float invN = 1.f / (float)Nn;
    float mu = g_bnsum[c] * invN;
    float var = g_bnsum[128 + c] * invN - mu * mu;
    float rs = rsqrtf(var + EPSBN);
    out[(size_t)n * ldo + c] = (y[idx] - mu) * rs * g[c] + b[c];
}

// ---------------- decoder final dot ----------------
__global__ void k_dec_out(const float* __restrict__ t, const float* __restrict__ W2,
                          const float* __restrict__ b2, float* __restrict__ out) {
    int warp = (blockIdx.x * blockDim.x + threadIdx.x) >> 5;
    if (warp >= Nn) return;
    int lane = threadIdx.x & 31;
    float4 tv = ((const float4*)t)[(size_t)warp * 32 + lane];
    float4 wv = ((const float4*)W2)[lane];
    float s = tv.x * wv.x + tv.y * wv.y + tv.z * wv.z + tv.w * wv.w;
#pragma unroll
    for (int o = 16; o; o >>= 1) s += __shfl_down_sync(0xffffffffu, s, o);
    if (lane == 0) out[warp] = s + b2[0];
}

// ---------------- launch ----------------
extern "C" void kernel_launch(void* const* d_in, const int* in_sizes, int n_in,
                              void* d_out, int out_size) {
    const float* x      = (const float*)d_in[0];
    const int*   src    = (const int*)d_in[1];
    const int*   dst    = (const int*)d_in[2];
    const float* emb_W1 = (const float*)d_in[3];
    const float* emb_b1 = (const float*)d_in[4];
    const float* emb_W2 = (const float*)d_in[5];
    const float* emb_b2 = (const float*)d_in[6];
    const float* emb_Ws = (const float*)d_in[7];
    const float* emb_bs = (const float*)d_in[8];
    const float* gat_W  = (const float*)d_in[9];
    const float* gat_al = (const float*)d_in[10];
    const float* gat_ar = (const float*)d_in[11];
    const float* gat_b  = (const float*)d_in[12];
    const float* bn1_g  = (const float*)d_in[13];
    const float* bn1_b  = (const float*)d_in[14];
    const float* ff_W1  = (const float*)d_in[15];
    const float* ff_b1  = (const float*)d_in[16];
    const float* ff_W2  = (const float*)d_in[17];
    const float* ff_b2  = (const float*)d_in[18];
    const float* bn2_g  = (const float*)d_in[19];
    const float* bn2_b  = (const float*)d_in[20];
    const float* dec_W1 = (const float*)d_in[21];
    const float* dec_b1 = (const float*)d_in[22];
    const float* dec_W2 = (const float*)d_in[23];
    const float* dec_b2 = (const float*)d_in[24];

    void* p;
    float *HC, *zb, *tb, *yb, *hm, *bns;
    int* degp;
    cudaGetSymbolAddress(&p, g_HC);    HC = (float*)p;
    cudaGetSymbolAddress(&p, g_z);     zb = (float*)p;
    cudaGetSymbolAddress(&p, g_t);     tb = (float*)p;
    cudaGetSymbolAddress(&p, g_y);     yb = (float*)p;
    cudaGetSymbolAddress(&p, g_hmid);  hm = (float*)p;
    cudaGetSymbolAddress(&p, g_bnsum); bns = (float*)p;
    cudaGetSymbolAddress(&p, g_deg);   degp = (int*)p;

    // --- CSR build (by dst) ---
    cudaMemsetAsync(degp, 0, Nn * sizeof(int));
    k_count<<<(Ee + 255) / 256, 256>>>(dst);
    const int nb = (Nn + 1023) / 1024;  // 98
    k_scan1<<<nb, 1024>>>();
    k_scan2<<<1, 128>>>(nb);
    k_finalize<<<(Nn + 255) / 256, 256>>>();
    k_fill<<<(Ee + 255) / 256, 256>>>(dst);

    // --- embed ---
    k_embed<<<Nn, 128>>>(x, emb_W1, emb_b1, emb_W2, emb_b2, emb_Ws, emb_bs);

    dim3 grid1((Nn + 127) / 128, 1);
    dim3 grid2((Nn + 127) / 128, 2);
    const int bnApplyBlocks = (Nn * 128 + 255) / 256;
    const int warpBlocks = (Nn * 32 + 255) / 256;

    for (int l = 0; l < 4; l++) {
        const float* h = HC + l * 128;
        // z = h @ gat_W[l]
        k_sgemm<false, false, false><<<grid1, 256>>>(h, 640, gat_W + (size_t)l * 128 * 128,
                                                     nullptr, nullptr, 0, zb, 128, Nn, 128, 128);
        k_eler<<<(Nn * 16 + 255) / 256, 256>>>(zb, gat_al + l * 128, gat_ar + l * 128);
        k_gat<<<warpBlocks, 256>>>(zb, src, h, 640, gat_b + l * 128, yb);
        // BN1
        cudaMemsetAsync(bns, 0, 256 * sizeof(float));
        k_bn_stats<<<512, 128>>>(yb);
        k_bn_apply<<<bnApplyBlocks, 256>>>(yb, bn1_g + l * 128, bn1_b + l * 128, hm, 128);
        // FF
        k_sgemm<true, true, false><<<grid2, 256>>>(hm, 128, ff_W1 + (size_t)l * 128 * 256,
                                                   ff_b1 + l * 256, nullptr, 0, tb, 256, Nn, 128, 256);
        k_sgemm<false, true, true><<<grid1, 256>>>(tb, 256, ff_W2 + (size_t)l * 256 * 128,
                                                   ff_b2 + l * 128, hm, 128, yb, 128, Nn, 256, 128);
        // BN2 -> next column block of HC
        cudaMemsetAsync(bns, 0, 256 * sizeof(float));
        k_bn_stats<<<512, 128>>>(yb);
        k_bn_apply<<<bnApplyBlocks, 256>>>(yb, bn2_g + l * 128, bn2_b + l * 128,
                                           HC + (size_t)(l + 1) * 128, 640);
    }

    // --- decoder ---
    k_sgemm<true, true, false><<<grid1, 256>>>(HC, 640, dec_W1, dec_b1, nullptr, 0,
                                               tb, 128, Nn, 640, 128);
    k_dec_out<<<warpBlocks, 256>>>(tb, dec_W2, dec_b2, (float*)d_out);
}

// round 2
// speedup vs baseline: 1.4973x; 1.4973x over previous
#include <cuda_runtime.h>
#include <cstdint>

#define Nn 100000
#define Ee 600000
#define EPSBN 1e-5f
#define SLOPE 0.2f

// ---------------- scratch (device globals; no allocs allowed) ----------------
__device__ float g_HC[(size_t)Nn * 640];    // JumpingKnowledge buffer: 5 column blocks of 128
__device__ float g_z[(size_t)Nn * 128];     // GAT projection
__device__ float g_t[(size_t)Nn * 256];     // FF hidden / dec hidden
__device__ float g_y[(size_t)Nn * 128];     // pre-BN residual sum
__device__ float g_hmid[(size_t)Nn * 128];  // BN1 output
__device__ float g_el[(size_t)Nn * 16];
__device__ float g_er[(size_t)Nn * 16];
__device__ float g_bnsum[256];              // [0:128) sum, [128:256) sumsq
__device__ int   g_deg[Nn];
__device__ int   g_scan[Nn];
__device__ int   g_bsum[128];
__device__ int   g_rowptr[Nn + 1];
__device__ int   g_cursor[Nn];
__device__ int   g_eid[Ee];

// ---------------- CSR build ----------------
__global__ void k_count(const int* __restrict__ dst) {
    int e = blockIdx.x * blockDim.x + threadIdx.x;
    if (e < Ee) atomicAdd(&g_deg[dst[e]], 1);
}

__global__ void k_scan1() {
    __shared__ int s[1024];
    int i = blockIdx.x * 1024 + threadIdx.x;
    int v = (i < Nn) ? g_deg[i] : 0;
    s[threadIdx.x] = v;
    __syncthreads();
    for (int off = 1; off < 1024; off <<= 1) {
        int t = (threadIdx.x >= off) ? s[threadIdx.x - off] : 0;
        __syncthreads();
        s[threadIdx.x] += t;
        __syncthreads();
    }
    if (i < Nn) g_scan[i] = s[threadIdx.x];
    if (threadIdx.x == 1023) g_bsum[blockIdx.x] = s[1023];
}

__global__ void k_scan2(int nb) {
    __shared__ int s[128];
    int v = (threadIdx.x < nb) ? g_bsum[threadIdx.x] : 0;
    s[threadIdx.x] = v;
    __syncthreads();
    for (int off = 1; off < 128; off <<= 1) {
        int t = (threadIdx.x >= off) ? s[threadIdx.x - off] : 0;
        __syncthreads();
        s[threadIdx.x] += t;
        __syncthreads();
    }
    g_bsum[threadIdx.x] = (threadIdx.x == 0) ? 0 : s[threadIdx.x - 1];
}

__global__ void k_finalize() {
    int i = blockIdx.x * blockDim.x + threadIdx.x;
    if (i >= Nn) return;
    int incl = g_scan[i] + g_bsum[i >> 10];
    g_rowptr[i + 1] = incl;
    g_cursor[i] = incl - g_deg[i];
    if (i == 0) g_rowptr[0] = 0;
}

__global__ void k_fill(const int* __restrict__ dst) {
    int e = blockIdx.x * blockDim.x + threadIdx.x;
    if (e < Ee) {
        int d = dst[e];
        int p = atomicAdd(&g_cursor[d], 1);
        g_eid[p] = e;
    }
}

// ---------------- embed MLP (+skip) ----------------
__global__ void k_embed(const float* __restrict__ x,
                        const float* __restrict__ W1, const float* __restrict__ b1,
                        const float* __restrict__ W2, const float* __restrict__ b2,
                        const float* __restrict__ Ws, const float* __restrict__ bs) {
    __shared__ float t[128];
    int n = blockIdx.x, c = threadIdx.x;
    float x0 = x[n * 2], x1 = x[n * 2 + 1];
    float tv = x0 * W1[c] + x1 * W1[128 + c] + b1[c];
    t[c] = tv > 0.f ? tv : 0.f;
    __syncthreads();
    float acc = b2[c] + x0 * Ws[c] + x1 * Ws[128 + c] + bs[c];
#pragma unroll 8
    for (int k = 0; k < 128; k++) acc += t[k] * W2[k * 128 + c];
    g_HC[(size_t)n * 640 + c] = acc;
}

// ---------------- tf32 tensor-core GEMM: C = A[N,M] @ B[M,K] (+bias)(relu)(+res) ----------------
__device__ __forceinline__ float to_tf32(float x) {
    float r;
    asm("cvt.rna.tf32.f32 %0, %1;" : "=f"(r) : "f"(x));
    return r;
}

#define MMA_TF32(d, av, bv)                                               \
    asm volatile(                                                         \
        "mma.sync.aligned.m16n8k8.row.col.f32.tf32.tf32.f32 "             \
        "{%0,%1,%2,%3},{%4,%5,%6,%7},{%8,%9},{%0,%1,%2,%3};"              \
        : "+f"((d)[0]), "+f"((d)[1]), "+f"((d)[2]), "+f"((d)[3])          \
        : "r"((av)[0]), "r"((av)[1]), "r"((av)[2]), "r"((av)[3]),         \
          "r"((bv)[0]), "r"((bv)[1]))

// BM=128, BN=128, BK=16, 256 threads (8 warps), warp tile 32x64.
// As stride 20 floats -> conflict-free a-fragment LDS; Bs stride 136 -> conflict-free b-fragment LDS.
template <bool RELU, bool HAS_BIAS, bool HAS_RES>
__global__ void __launch_bounds__(256) k_tgemm(
    const float* __restrict__ A, int lda,
    const float* __restrict__ B,  // row-major [Mred, Kcols]
    const float* __restrict__ bias,
    const float* __restrict__ Res, int ldres,
    float* __restrict__ C, int ldc,
    int Nrows, int Mred, int Kcols) {
    __shared__ float As[2][128 * 20];
    __shared__ float Bs[2][16 * 136];

    const int tid = threadIdx.x;
    const int lane = tid & 31;
    const int wid = tid >> 5;
    const int bm = blockIdx.x * 128;
    const int bn = blockIdx.y * 128;

    const int m0 = (wid & 3) * 32;
    const int n0 = (wid >> 2) * 64;
    const int qrow = lane >> 2;  // 0..7
    const int qk = lane & 3;     // 0..3

    // global load mapping
    const int arow = tid >> 1;            // 0..127
    const int aseg = (tid & 1) * 8;       // 0 or 8
    const int brow = tid >> 4;            // 0..15
    const int bcol = (tid & 15) * 8;      // 0..120

    float acc[2][8][4];
#pragma unroll
    for (int mi = 0; mi < 2; mi++)
#pragma unroll
        for (int ni = 0; ni < 8; ni++)
#pragma unroll
            for (int j = 0; j < 4; j++) acc[mi][ni][j] = 0.f;

    const int nIter = Mred >> 4;
    const bool arow_ok = (bm + arow) < Nrows;
    const float* Arow = A + (size_t)(bm + arow) * lda + aseg;

    float4 la0, la1, lb0, lb1;

    // prologue: load tile 0
    {
        la0 = make_float4(0.f, 0.f, 0.f, 0.f);
        la1 = la0;
        if (arow_ok) {
            la0 = *(const float4*)(Arow + 0);
            la1 = *(const float4*)(Arow + 4);
        }
        const float* Bp = B + (size_t)brow * Kcols + bn + bcol;
        lb0 = *(const float4*)(Bp + 0);
        lb1 = *(const float4*)(Bp + 4);
        float* as = &As[0][arow * 20 + aseg];
        as[0] = to_tf32(la0.x); as[1] = to_tf32(la0.y);
        as[2] = to_tf32(la0.z); as[3] = to_tf32(la0.w);
        as[4] = to_tf32(la1.x); as[5] = to_tf32(la1.y);
        as[6] = to_tf32(la1.z); as[7] = to_tf32(la1.w);
        float* bs = &Bs[0][brow * 136 + bcol];
        bs[0] = to_tf32(lb0.x); bs[1] = to_tf32(lb0.y);
        bs[2] = to_tf32(lb0.z); bs[3] = to_tf32(lb0.w);
        bs[4] = to_tf32(lb1.x); bs[5] = to_tf32(lb1.y);
        bs[6] = to_tf32(lb1.z); bs[7] = to_tf32(lb1.w);
    }
    __syncthreads();

    for (int it = 0; it < nIter; it++) {
        const int cur = it & 1;
        const bool hasNext = (it + 1) < nIter;
        if (hasNext) {
            int kt = (it + 1) << 4;
            la0 = make_float4(0.f, 0.f, 0.f, 0.f);
            la1 = la0;
            if (arow_ok) {
                la0 = *(const float4*)(Arow + kt + 0);
                la1 = *(const float4*)(Arow + kt + 4);
            }
            const float* Bp = B + (size_t)(kt + brow) * Kcols + bn + bcol;
            lb0 = *(const float4*)(Bp + 0);
            lb1 = *(const float4*)(Bp + 4);
        }

        const float* as = As[cur];
        const float* bs = Bs[cur];
#pragma unroll
        for (int ks = 0; ks < 2; ks++) {
            const int kbase = ks * 8;
            uint32_t a[2][4];
#pragma unroll
            for (int mi = 0; mi < 2; mi++) {
                const float* ap = as + (m0 + mi * 16 + qrow) * 20 + kbase + qk;
                a[mi][0] = __float_as_uint(ap[0]);
                a[mi][1] = __float_as_uint(ap[8 * 20]);
                a[mi][2] = __float_as_uint(ap[4]);
                a[mi][3] = __float_as_uint(ap[8 * 20 + 4]);
            }
            uint32_t b[8][2];
#pragma unroll
            for (int ni = 0; ni < 8; ni++) {
                const float* bp = bs + (kbase + qk) * 136 + n0 + ni * 8 + qrow;
                b[ni][0] = __float_as_uint(bp[0]);
                b[ni][1] = __float_as_uint(bp[4 * 136]);
            }
#pragma unroll
            for (int mi = 0; mi < 2; mi++)
#pragma unroll
                for (int ni = 0; ni < 8; ni++) MMA_TF32(acc[mi][ni], a[mi], b[ni]);
        }

        if (hasNext) {
            float* asn = &As[cur ^ 1][arow * 20 + aseg];
            asn[0] = to_tf32(la0.x); asn[1] = to_tf32(la0.y);
            asn[2] = to_tf32(la0.z); asn[3] = to_tf32(la0.w);
            asn[4] = to_tf32(la1.x); asn[5] = to_tf32(la1.y);
            asn[6] = to_tf32(la1.z); asn[7] = to_tf32(la1.w);
            float* bsn = &Bs[cur ^ 1][brow * 136 + bcol];
            bsn[0] = to_tf32(lb0.x); bsn[1] = to_tf32(lb0.y);
            bsn[2] = to_tf32(lb0.z); bsn[3] = to_tf32(lb0.w);
            bsn[4] = to_tf32(lb1.x); bsn[5] = to_tf32(lb1.y);
            bsn[6] = to_tf32(lb1.z); bsn[7] = to_tf32(lb1.w);
            __syncthreads();
        }
    }

    // epilogue
#pragma unroll
    for (int mi = 0; mi < 2; mi++) {
#pragma unroll
        for (int half = 0; half < 2; half++) {
            int r = bm + m0 + mi * 16 + qrow + half * 8;
            if (r >= Nrows) continue;
#pragma unroll
            for (int ni = 0; ni < 8; ni++) {
                int gc = bn + n0 + ni * 8 + qk * 2;
                float v0 = acc[mi][ni][half * 2 + 0];
                float v1 = acc[mi][ni][half * 2 + 1];
                if (HAS_BIAS) {
                    v0 += bias[gc];
                    v1 += bias[gc + 1];
                }
                if (RELU) {
                    v0 = fmaxf(v0, 0.f);
                    v1 = fmaxf(v1, 0.f);
                }
                if (HAS_RES) {
                    const float* rp = Res + (size_t)r * ldres + gc;
                    v0 += rp[0];
                    v1 += rp[1];
                }
                float2 o = make_float2(v0, v1);
                *(float2*)(C + (size_t)r * ldc + gc) = o;
            }
        }
    }
}

// ---------------- el / er ----------------
__global__ void k_eler(const float* __restrict__ z, const float* __restrict__ al,
                       const float* __restrict__ ar) {
    int t = blockIdx.x * blockDim.x + threadIdx.x;
    if (t >= Nn * 16) return;
    int n = t >> 4, h = t & 15;
    const float* zr = z + (size_t)n * 128 + h * 8;
    const float* a = al + h * 8;
    const float* r = ar + h * 8;
    float sl = 0.f, sr = 0.f;
#pragma unroll
    for (int d = 0; d < 8; d++) {
        float zv = zr[d];
        sl += zv * a[d];
        sr += zv * r[d];
    }
    g_el[t] = sl;
    g_er[t] = sr;
}

// ---------------- GAT aggregate (warp per node) + residual + bias -> y ----------------
__global__ void k_gat(const float* __restrict__ z, const int* __restrict__ src,
                      const float* __restrict__ hres, int ldh,
                      const float* __restrict__ bias, float* __restrict__ y) {
    int warp = (blockIdx.x * blockDim.x + threadIdx.x) >> 5;
    if (warp >= Nn) return;
    int lane = threadIdx.x & 31;
    int head = lane >> 1;
    int beg = g_rowptr[warp], end = g_rowptr[warp + 1];
    float er_h = g_er[warp * 16 + head];

    float m = -1e30f;
    for (int i = beg; i < end; i++) {
        int s = src[g_eid[i]];
        float v = g_el[s * 16 + head] + er_h;
        v = v > 0.f ? v : SLOPE * v;
        m = fmaxf(m, v);
    }
    float den = 0.f;
    float4 acc = make_float4(0.f, 0.f, 0.f, 0.f);
    const float4* z4 = (const float4*)z;
    for (int i = beg; i < end; i++) {
        int s = src[g_eid[i]];
        float v = g_el[s * 16 + head] + er_h;
        v = v > 0.f ? v : SLOPE * v;
        float w = expf(v - m);
        den += w;
        float4 zv = z4[(size_t)s * 32 + lane];
        acc.x += w * zv.x; acc.y += w * zv.y; acc.z += w * zv.z; acc.w += w * zv.w;
    }
    float dinv = den > 0.f ? 1.f / den : 1.f;
    float4 b4 = ((const float4*)bias)[lane];
    float4 h4 = *(const float4*)(hres + (size_t)warp * ldh + lane * 4);
    float4 o;
    o.x = acc.x * dinv + b4.x + h4.x;
    o.y = acc.y * dinv + b4.y + h4.y;
    o.z = acc.z * dinv + b4.z + h4.z;
    o.w = acc.w * dinv + b4.w + h4.w;
    ((float4*)y)[(size_t)warp * 32 + lane] = o;
}

// ---------------- BatchNorm ----------------
__global__ void k_bn_stats(const float* __restrict__ y) {
    int c = threadIdx.x;
    float s = 0.f, s2 = 0.f;
    for (int n = blockIdx.x; n < Nn; n += gridDim.x) {
        float v = y[(size_t)n * 128 + c];
        s += v;
        s2 += v * v;
    }
    atomicAdd(&g_bnsum[c], s);
    atomicAdd(&g_bnsum[128 + c], s2);
}

__global__ void k_bn_apply(const float* __restrict__ y, const float* __restrict__ g,
                           const float* __restrict__ b, float* __restrict__ out, int ldo) {
    int idx = blockIdx.x * blockDim.x + threadIdx.x;
    if (idx >= Nn * 128) return;
    int n = idx >> 7, c = idx & 127;
    const float invN = 1.f / (float)Nn;
    float mu = g_bnsum[c] * invN;
    float var = g_bnsum[128 + c] * invN - mu * mu;
    float rs = rsqrtf(var + EPSBN);
    out[(size_t)n * ldo + c] = (y[idx] - mu) * rs * g[c] + b[c];
}

// ---------------- decoder final dot ----------------
__global__ void k_dec_out(const float* __restrict__ t, const float* __restrict__ W2,
                          const float* __restrict__ b2, float* __restrict__ out) {
    int warp = (blockIdx.x * blockDim.x + threadIdx.x) >> 5;
    if (warp >= Nn) return;
    int lane = threadIdx.x & 31;
    float4 tv = ((const float4*)t)[(size_t)warp * 32 + lane];
    float4 wv = ((const float4*)W2)[lane];
    float s = tv.x * wv.x + tv.y * wv.y + tv.z * wv.z + tv.w * wv.w;
#pragma unroll
    for (int o = 16; o; o >>= 1) s += __shfl_down_sync(0xffffffffu, s, o);
    if (lane == 0) out[warp] = s + b2[0];
}

// ---------------- launch ----------------
extern "C" void kernel_launch(void* const* d_in, const int* in_sizes, int n_in,
                              void* d_out, int out_size) {
    const float* x      = (const float*)d_in[0];
    const int*   src    = (const int*)d_in[1];
    const int*   dst    = (const int*)d_in[2];
    const float* emb_W1 = (const float*)d_in[3];
    const float* emb_b1 = (const float*)d_in[4];
    const float* emb_W2 = (const float*)d_in[5];
    const float* emb_b2 = (const float*)d_in[6];
    const float* emb_Ws = (const float*)d_in[7];
    const float* emb_bs = (const float*)d_in[8];
    const float* gat_W  = (const float*)d_in[9];
    const float* gat_al = (const float*)d_in[10];
    const float* gat_ar = (const float*)d_in[11];
    const float* gat_b  = (const float*)d_in[12];
    const float* bn1_g  = (const float*)d_in[13];
    const float* bn1_b  = (const float*)d_in[14];
    const float* ff_W1  = (const float*)d_in[15];
    const float* ff_b1  = (const float*)d_in[16];
    const float* ff_W2  = (const float*)d_in[17];
    const float* ff_b2  = (const float*)d_in[18];
    const float* bn2_g  = (const float*)d_in[19];
    const float* bn2_b  = (const float*)d_in[20];
    const float* dec_W1 = (const float*)d_in[21];
    const float* dec_b1 = (const float*)d_in[22];
    const float* dec_W2 = (const float*)d_in[23];
    const float* dec_b2 = (const float*)d_in[24];

    void* p;
    float *HC, *zb, *tb, *yb, *hm, *bns;
    int* degp;
    cudaGetSymbolAddress(&p, g_HC);    HC = (float*)p;
    cudaGetSymbolAddress(&p, g_z);     zb = (float*)p;
    cudaGetSymbolAddress(&p, g_t);     tb = (float*)p;
    cudaGetSymbolAddress(&p, g_y);     yb = (float*)p;
    cudaGetSymbolAddress(&p, g_hmid);  hm = (float*)p;
    cudaGetSymbolAddress(&p, g_bnsum); bns = (float*)p;
    cudaGetSymbolAddress(&p, g_deg);   degp = (int*)p;

    // --- CSR build (by dst) ---
    cudaMemsetAsync(degp, 0, Nn * sizeof(int));
    k_count<<<(Ee + 255) / 256, 256>>>(dst);
    const int nb = (Nn + 1023) / 1024;  // 98
    k_scan1<<<nb, 1024>>>();
    k_scan2<<<1, 128>>>(nb);
    k_finalize<<<(Nn + 255) / 256, 256>>>();
    k_fill<<<(Ee + 255) / 256, 256>>>(dst);

    // --- embed ---
    k_embed<<<Nn, 128>>>(x, emb_W1, emb_b1, emb_W2, emb_b2, emb_Ws, emb_bs);

    dim3 grid1((Nn + 127) / 128, 1);
    dim3 grid2((Nn + 127) / 128, 2);
    const int bnApplyBlocks = (Nn * 128 + 255) / 256;
    const int warpBlocks = (Nn * 32 + 255) / 256;

    for (int l = 0; l < 4; l++) {
        const float* h = HC + l * 128;
        // z = h @ gat_W[l]
        k_tgemm<false, false, false><<<grid1, 256>>>(h, 640, gat_W + (size_t)l * 128 * 128,
                                                     nullptr, nullptr, 0, zb, 128, Nn, 128, 128);
        k_eler<<<(Nn * 16 + 255) / 256, 256>>>(zb, gat_al + l * 128, gat_ar + l * 128);
        k_gat<<<warpBlocks, 256>>>(zb, src, h, 640, gat_b + l * 128, yb);
        // BN1
        cudaMemsetAsync(bns, 0, 256 * sizeof(float));
        k_bn_stats<<<512, 128>>>(yb);
        k_bn_apply<<<bnApplyBlocks, 256>>>(yb, bn1_g + l * 128, bn1_b + l * 128, hm, 128);
        // FF
        k_tgemm<true, true, false><<<grid2, 256>>>(hm, 128, ff_W1 + (size_t)l * 128 * 256,
                                                   ff_b1 + l * 256, nullptr, 0, tb, 256, Nn, 128, 256);
        k_tgemm<false, true, true><<<grid1, 256>>>(tb, 256, ff_W2 + (size_t)l * 256 * 128,
                                                   ff_b2 + l * 128, hm, 128, yb, 128, Nn, 256, 128);
        // BN2 -> next column block of HC
        cudaMemsetAsync(bns, 0, 256 * sizeof(float));
        k_bn_stats<<<512, 128>>>(yb);
        k_bn_apply<<<bnApplyBlocks, 256>>>(yb, bn2_g + l * 128, bn2_b + l * 128,
                                           HC + (size_t)(l + 1) * 128, 640);
    }

    // --- decoder ---
    k_tgemm<true, true, false><<<grid1, 256>>>(HC, 640, dec_W1, dec_b1, nullptr, 0,
                                               tb, 128, Nn, 640, 128);
    k_dec_out<<<warpBlocks, 256>>>(tb, dec_W2, dec_b2, (float*)d_out);
}

// round 4
// speedup vs baseline: 1.5627x; 1.0437x over previous
#include <cuda_runtime.h>
#include <cstdint>

#define Nn 100000
#define Ee 600000
#define EPSBN 1e-5f
#define SLOPE 0.2f

// ---------------- scratch (device globals; no allocs allowed) ----------------
__device__ float g_HC[(size_t)Nn * 640];
__device__ float g_z[(size_t)Nn * 128];
__device__ float g_t[(size_t)Nn * 256];
__device__ float g_y[(size_t)Nn * 128];
__device__ float g_hmid[(size_t)Nn * 128];
__device__ float g_el[(size_t)Nn * 16];
__device__ float g_er[(size_t)Nn * 16];
__device__ float g_bnsum[256];
__device__ int   g_deg[Nn];
__device__ int   g_scan[Nn];
__device__ int   g_bsum[128];
__device__ int   g_rowptr[Nn + 1];
__device__ int   g_cursor[Nn];
__device__ int   g_eid[Ee];
// tf32-rounded weights (same layout as inputs): gat[65536] ff1[131072] ff2[131072] dec[81920]
__device__ float g_W[409600];

__device__ __forceinline__ float to_tf32(float x) {
    float r;
    asm("cvt.rna.tf32.f32 %0, %1;" : "=f"(r) : "f"(x));
    return r;
}
__device__ __forceinline__ uint32_t smem_to_u32(const void* p) {
    uint32_t a;
    asm("{ .reg .u64 t; cvta.to.shared.u64 t, %1; cvt.u32.u64 %0, t; }" : "=r"(a) : "l"(p));
    return a;
}
__device__ __forceinline__ void cp16(uint32_t dst, const void* src, bool ok) {
    int sz = ok ? 16 : 0;
    asm volatile("cp.async.cg.shared.global [%0], [%1], 16, %2;"
                 :: "r"(dst), "l"(src), "r"(sz) : "memory");
}
#define CP_COMMIT() asm volatile("cp.async.commit_group;" ::: "memory")
#define CP_WAIT2() asm volatile("cp.async.wait_group 2;" ::: "memory")

#define MMA_TF32(d, av, bv)                                               \
    asm volatile(                                                         \
        "mma.sync.aligned.m16n8k8.row.col.f32.tf32.tf32.f32 "             \
        "{%0,%1,%2,%3},{%4,%5,%6,%7},{%8,%9},{%0,%1,%2,%3};"              \
        : "+f"((d)[0]), "+f"((d)[1]), "+f"((d)[2]), "+f"((d)[3])          \
        : "r"((av)[0]), "r"((av)[1]), "r"((av)[2]), "r"((av)[3]),         \
          "r"((bv)[0]), "r"((bv)[1]))

// ---------------- CSR build ----------------
__global__ void k_count(const int* __restrict__ dst) {
    int e = blockIdx.x * blockDim.x + threadIdx.x;
    if (e < Ee) atomicAdd(&g_deg[dst[e]], 1);
}
__global__ void k_scan1() {
    __shared__ int s[1024];
    int i = blockIdx.x * 1024 + threadIdx.x;
    int v = (i < Nn) ? g_deg[i] : 0;
    s[threadIdx.x] = v;
    __syncthreads();
    for (int off = 1; off < 1024; off <<= 1) {
        int t = (threadIdx.x >= off) ? s[threadIdx.x - off] : 0;
        __syncthreads();
        s[threadIdx.x] += t;
        __syncthreads();
    }
    if (i < Nn) g_scan[i] = s[threadIdx.x];
    if (threadIdx.x == 1023) g_bsum[blockIdx.x] = s[1023];
}
__global__ void k_scan2(int nb) {
    __shared__ int s[128];
    int v = (threadIdx.x < nb) ? g_bsum[threadIdx.x] : 0;
    s[threadIdx.x] = v;
    __syncthreads();
    for (int off = 1; off < 128; off <<= 1) {
        int t = (threadIdx.x >= off) ? s[threadIdx.x - off] : 0;
        __syncthreads();
        s[threadIdx.x] += t;
        __syncthreads();
    }
    g_bsum[threadIdx.x] = (threadIdx.x == 0) ? 0 : s[threadIdx.x - 1];
}
__global__ void k_finalize() {
    int i = blockIdx.x * blockDim.x + threadIdx.x;
    if (i >= Nn) return;
    int incl = g_scan[i] + g_bsum[i >> 10];
    g_rowptr[i + 1] = incl;
    g_cursor[i] = incl - g_deg[i];
    if (i == 0) g_rowptr[0] = 0;
}
__global__ void k_fill(const int* __restrict__ dst) {
    int e = blockIdx.x * blockDim.x + threadIdx.x;
    if (e < Ee) {
        int d = dst[e];
        int p = atomicAdd(&g_cursor[d], 1);
        g_eid[p] = e;
    }
}

// ---------------- weight cvt (rna tf32, layout preserved) ----------------
__global__ void k_cvt(const float* __restrict__ in, float* __restrict__ out, int n) {
    int i = blockIdx.x * blockDim.x + threadIdx.x;
    if (i < n) out[i] = to_tf32(in[i]);
}

// ---------------- embed MLP (+skip) ----------------
__global__ void k_embed(const float* __restrict__ x,
                        const float* __restrict__ W1, const float* __restrict__ b1,
                        const float* __restrict__ W2, const float* __restrict__ b2,
                        const float* __restrict__ Ws, const float* __restrict__ bs) {
    __shared__ float t[128];
    int n = blockIdx.x, c = threadIdx.x;
    float x0 = x[n * 2], x1 = x[n * 2 + 1];
    float tv = x0 * W1[c] + x1 * W1[128 + c] + b1[c];
    t[c] = tv > 0.f ? tv : 0.f;
    __syncthreads();
    float acc = b2[c] + x0 * Ws[c] + x1 * Ws[128 + c] + bs[c];
#pragma unroll 8
    for (int k = 0; k < 128; k++) acc += t[k] * W2[k * 128 + c];
    g_HC[(size_t)n * 640 + c] = acc;
}

// ---------------- tf32 tensor GEMM, cp.async 4-stage pipeline ----------------
// C = A[N,Mred] @ B[Mred,Kcols] (+bias)(relu)(+res). B pre-rounded to tf32.
// BM=128, BN=128, BK=16, 256 threads (8 warps), warp tile 32x64.
// As stage layout [128][20] (pad), Bs stage layout [16][136] (pad).
template <bool RELU, bool HAS_BIAS, bool HAS_RES>
__global__ void __launch_bounds__(256) k_tgemm(
    const float* __restrict__ A, int lda,
    const float* __restrict__ B,
    const float* __restrict__ bias,
    const float* __restrict__ Res, int ldres,
    float* __restrict__ C, int ldc,
    int Nrows, int Mred, int Kcols) {
    constexpr int S = 4;
    constexpr int ASTG = 128 * 20;  // floats per A stage
    constexpr int BSTG = 16 * 136;  // floats per B stage
    extern __shared__ float sm[];
    float* AsF = sm;               // S * ASTG
    float* BsF = sm + S * ASTG;    // S * BSTG

    const int tid = threadIdx.x;
    const int lane = tid & 31;
    const int wid = tid >> 5;
    const int bm = blockIdx.x * 128;
    const int bn = blockIdx.y * 128;

    const int m0 = (wid & 3) * 32;
    const int n0 = (wid >> 2) * 64;
    const int qrow = lane >> 2;
    const int qk = lane & 3;

    // loader mapping
    const int arow = tid >> 1;        // 0..127
    const int aseg = (tid & 1) * 8;   // 0 or 8
    const int brow = tid >> 4;        // 0..15
    const int bcol = (tid & 15) * 8;  // 0..120

    const int gr = bm + arow;
    const bool aok = gr < Nrows;
    const float* Asrc = A + (size_t)gr * lda + aseg;
    const float* Bsrc = B + (size_t)brow * Kcols + bn + bcol;
    const uint32_t adst = smem_to_u32(AsF) + (uint32_t)(arow * 20 + aseg) * 4u;
    const uint32_t bdst = smem_to_u32(BsF) + (uint32_t)(brow * 136 + bcol) * 4u;

    float acc[2][8][4];
#pragma unroll
    for (int mi = 0; mi < 2; mi++)
#pragma unroll
        for (int ni = 0; ni < 8; ni++)
#pragma unroll
            for (int j = 0; j < 4; j++) acc[mi][ni][j] = 0.f;

    const int nIter = Mred >> 4;

    // prologue: stages 0..S-2
#pragma unroll
    for (int s = 0; s < S - 1; s++) {
        if (s < nIter) {
            int kt = s << 4;
            cp16(adst + (uint32_t)(s * ASTG) * 4u, Asrc + kt, aok);
            cp16(adst + (uint32_t)(s * ASTG) * 4u + 16u, Asrc + kt + 4, aok);
            cp16(bdst + (uint32_t)(s * BSTG) * 4u, Bsrc + (size_t)kt * Kcols, true);
            cp16(bdst + (uint32_t)(s * BSTG) * 4u + 16u, Bsrc + (size_t)kt * Kcols + 4, true);
        }
        CP_COMMIT();
    }

    for (int it = 0; it < nIter; it++) {
        CP_WAIT2();
        __syncthreads();

        const int stg = it & (S - 1);
        const float* as = AsF + stg * ASTG;
        const float* bs = BsF + stg * BSTG;
#pragma unroll
        for (int ks = 0; ks < 2; ks++) {
            const int kbase = ks * 8;
            uint32_t a[2][4];
#pragma unroll
            for (int mi = 0; mi < 2; mi++) {
                const float* ap = as + (m0 + mi * 16 + qrow) * 20 + kbase + qk;
                a[mi][0] = __float_as_uint(ap[0]);
                a[mi][1] = __float_as_uint(ap[8 * 20]);
                a[mi][2] = __float_as_uint(ap[4]);
                a[mi][3] = __float_as_uint(ap[8 * 20 + 4]);
            }
            uint32_t b[8][2];
#pragma unroll
            for (int ni = 0; ni < 8; ni++) {
                const float* bp = bs + (kbase + qk) * 136 + n0 + ni * 8 + qrow;
                b[ni][0] = __float_as_uint(bp[0]);
                b[ni][1] = __float_as_uint(bp[4 * 136]);
            }
#pragma unroll
            for (int mi = 0; mi < 2; mi++)
#pragma unroll
                for (int ni = 0; ni < 8; ni++) MMA_TF32(acc[mi][ni], a[mi], b[ni]);
        }
        __syncthreads();

        const int nx = it + S - 1;
        if (nx < nIter) {
            const int s = nx & (S - 1);
            const int kt = nx << 4;
            cp16(adst + (uint32_t)(s * ASTG) * 4u, Asrc + kt, aok);
            cp16(adst + (uint32_t)(s * ASTG) * 4u + 16u, Asrc + kt + 4, aok);
            cp16(bdst + (uint32_t)(s * BSTG) * 4u, Bsrc + (size_t)kt * Kcols, true);
            cp16(bdst + (uint32_t)(s * BSTG) * 4u + 16u, Bsrc + (size_t)kt * Kcols + 4, true);
        }
        CP_COMMIT();
    }

    // epilogue
#pragma unroll
    for (int mi = 0; mi < 2; mi++) {
#pragma unroll
        for (int half = 0; half < 2; half++) {
            int r = bm + m0 + mi * 16 + qrow + half * 8;
            if (r >= Nrows) continue;
#pragma unroll
            for (int ni = 0; ni < 8; ni++) {
                int gc = bn + n0 + ni * 8 + qk * 2;
                float v0 = acc[mi][ni][half * 2 + 0];
                float v1 = acc[mi][ni][half * 2 + 1];
                if (HAS_BIAS) {
                    v0 += bias[gc];
                    v1 += bias[gc + 1];
                }
                if (RELU) {
                    v0 = fmaxf(v0, 0.f);
                    v1 = fmaxf(v1, 0.f);
                }
                if (HAS_RES) {
                    const float* rp = Res + (size_t)r * ldres + gc;
                    v0 += rp[0];
                    v1 += rp[1];
                }
                *(float2*)(C + (size_t)r * ldc + gc) = make_float2(v0, v1);
            }
        }
    }
}

// ---------------- el / er ----------------
__global__ void k_eler(const float* __restrict__ z, const float* __restrict__ al,
                       const float* __restrict__ ar) {
    int t = blockIdx.x * blockDim.x + threadIdx.x;
    if (t >= Nn * 16) return;
    int n = t >> 4, h = t & 15;
    const float* zr = z + (size_t)n * 128 + h * 8;
    const float* a = al + h * 8;
    const float* r = ar + h * 8;
    float sl = 0.f, sr = 0.f;
#pragma unroll
    for (int d = 0; d < 8; d++) {
        float zv = zr[d];
        sl += zv * a[d];
        sr += zv * r[d];
    }
    g_el[t] = sl;
    g_er[t] = sr;
}

// ---------------- GAT aggregate (warp per node) ----------------
__global__ void k_gat(const float* __restrict__ z, const int* __restrict__ src,
                      const float* __restrict__ hres, int ldh,
                      const float* __restrict__ bias, float* __restrict__ y) {
    int warp = (blockIdx.x * blockDim.x + threadIdx.x) >> 5;
    if (warp >= Nn) return;
    int lane = threadIdx.x & 31;
    int head = lane >> 1;
    int beg = g_rowptr[warp], end = g_rowptr[warp + 1];
    float er_h = g_er[warp * 16 + head];

    float m = -1e30f;
    for (int i = beg; i < end; i++) {
        int s = src[g_eid[i]];
        float v = g_el[s * 16 + head] + er_h;
        v = v > 0.f ? v : SLOPE * v;
        m = fmaxf(m, v);
    }
    float den = 0.f;
    float4 acc = make_float4(0.f, 0.f, 0.f, 0.f);
    const float4* z4 = (const float4*)z;
    for (int i = beg; i < end; i++) {
        int s = src[g_eid[i]];
        float v = g_el[s * 16 + head] + er_h;
        v = v > 0.f ? v : SLOPE * v;
        float w = expf(v - m);
        den += w;
        float4 zv = z4[(size_t)s * 32 + lane];
        acc.x += w * zv.x; acc.y += w * zv.y; acc.z += w * zv.z; acc.w += w * zv.w;
    }
    float dinv = den > 0.f ? 1.f / den : 1.f;
    float4 b4 = ((const float4*)bias)[lane];
    float4 h4 = *(const float4*)(hres + (size_t)warp * ldh + lane * 4);
    float4 o;
    o.x = acc.x * dinv + b4.x + h4.x;
    o.y = acc.y * dinv + b4.y + h4.y;
    o.z = acc.z * dinv + b4.z + h4.z;
    o.w = acc.w * dinv + b4.w + h4.w;
    ((float4*)y)[(size_t)warp * 32 + lane] = o;
}

// ---------------- BatchNorm ----------------
__global__ void k_bn_stats(const float* __restrict__ y) {
    int c = threadIdx.x;
    float s = 0.f, s2 = 0.f;
    for (int n = blockIdx.x; n < Nn; n += gridDim.x) {
        float v = y[(size_t)n * 128 + c];
        s += v;
        s2 += v * v;
    }
    atomicAdd(&g_bnsum[c], s);
    atomicAdd(&g_bnsum[128 + c], s2);
}
__global__ void k_bn_apply(const float* __restrict__ y, const float* __restrict__ g,
                           const float* __restrict__ b, float* __restrict__ out, int ldo) {
    int idx = blockIdx.x * blockDim.x + threadIdx.x;
    if (idx >= Nn * 128) return;
    int n = idx >> 7, c = idx & 127;
    const float invN = 1.f / (float)Nn;
    float mu = g_bnsum[c] * invN;
    float var = g_bnsum[128 + c] * invN - mu * mu;
    float rs = rsqrtf(var + EPSBN);
    out[(size_t)n * ldo + c] = (y[idx] - mu) * rs * g[c] + b[c];
}

// ---------------- decoder final dot ----------------
__global__ void k_dec_out(const float* __restrict__ t, const float* __restrict__ W2,
                          const float* __restrict__ b2, float* __restrict__ out) {
    int warp = (blockIdx.x * blockDim.x + threadIdx.x) >> 5;
    if (warp >= Nn) return;
    int lane = threadIdx.x & 31;
    float4 tv = ((const float4*)t)[(size_t)warp * 32 + lane];
    float4 wv = ((const float4*)W2)[lane];
    float s = tv.x * wv.x + tv.y * wv.y + tv.z * wv.z + tv.w * wv.w;
#pragma unroll
    for (int o = 16; o; o >>= 1) s += __shfl_down_sync(0xffffffffu, s, o);
    if (lane == 0) out[warp] = s + b2[0];
}

// ---------------- launch ----------------
extern "C" void kernel_launch(void* const* d_in, const int* in_sizes, int n_in,
                              void* d_out, int out_size) {
    const float* x      = (const float*)d_in[0];
    const int*   src    = (const int*)d_in[1];
    const int*   dst    = (const int*)d_in[2];
    const float* emb_W1 = (const float*)d_in[3];
    const float* emb_b1 = (const float*)d_in[4];
    const float* emb_W2 = (const float*)d_in[5];
    const float* emb_b2 = (const float*)d_in[6];
    const float* emb_Ws = (const float*)d_in[7];
    const float* emb_bs = (const float*)d_in[8];
    const float* gat_W  = (const float*)d_in[9];
    const float* gat_al = (const float*)d_in[10];
    const float* gat_ar = (const float*)d_in[11];
    const float* gat_b  = (const float*)d_in[12];
    const float* bn1_g  = (const float*)d_in[13];
    const float* bn1_b  = (const float*)d_in[14];
    const float* ff_W1  = (const float*)d_in[15];
    const float* ff_b1  = (const float*)d_in[16];
    const float* ff_W2  = (const float*)d_in[17];
    const float* ff_b2  = (const float*)d_in[18];
    const float* bn2_g  = (const float*)d_in[19];
    const float* bn2_b  = (const float*)d_in[20];
    const float* dec_W1 = (const float*)d_in[21];
    const float* dec_b1 = (const float*)d_in[22];
    const float* dec_W2 = (const float*)d_in[23];
    const float* dec_b2 = (const float*)d_in[24];

    void* p;
    float *HC, *zb, *tb, *yb, *hm, *bns, *W;
    int* degp;
    cudaGetSymbolAddress(&p, g_HC);    HC = (float*)p;
    cudaGetSymbolAddress(&p, g_z);     zb = (float*)p;
    cudaGetSymbolAddress(&p, g_t);     tb = (float*)p;
    cudaGetSymbolAddress(&p, g_y);     yb = (float*)p;
    cudaGetSymbolAddress(&p, g_hmid);  hm = (float*)p;
    cudaGetSymbolAddress(&p, g_bnsum); bns = (float*)p;
    cudaGetSymbolAddress(&p, g_deg);   degp = (int*)p;
    cudaGetSymbolAddress(&p, g_W);     W = (float*)p;

    float* Wg = W;            // [4][128,128]
    float* Wf1 = W + 65536;   // [4][128,256]
    float* Wf2 = W + 196608;  // [4][256,128]
    float* Wd = W + 327680;   // [640,128]

    const int SMEM = (4 * 128 * 20 + 4 * 16 * 136) * 4;  // 75776 B
    static bool attrDone = false;
    if (!attrDone) {
        cudaFuncSetAttribute(k_tgemm<false, false, false>, cudaFuncAttributeMaxDynamicSharedMemorySize, SMEM);
        cudaFuncSetAttribute(k_tgemm<true, true, false>, cudaFuncAttributeMaxDynamicSharedMemorySize, SMEM);
        cudaFuncSetAttribute(k_tgemm<false, true, true>, cudaFuncAttributeMaxDynamicSharedMemorySize, SMEM);
        attrDone = true;
    }

    // launches 1-4: weight cvt (rna tf32)
    k_cvt<<<(65536 + 255) / 256, 256>>>(gat_W, Wg, 65536);
    k_cvt<<<(131072 + 255) / 256, 256>>>(ff_W1, Wf1, 131072);
    k_cvt<<<(131072 + 255) / 256, 256>>>(ff_W2, Wf2, 131072);
    k_cvt<<<(81920 + 255) / 256, 256>>>(dec_W1, Wd, 81920);

    // launch 5: embed
    k_embed<<<Nn, 128>>>(x, emb_W1, emb_b1, emb_W2, emb_b2, emb_Ws, emb_bs);

    const int gx = (Nn + 127) / 128;  // 782
    dim3 grid1(gx, 1), grid2(gx, 2);
    const int bnApplyBlocks = (Nn * 128 + 255) / 256;
    const int warpBlocks = (Nn * 32 + 255) / 256;

    // launch 6: layer-0 z GEMM (profiled by ncu -s 5 -c 1)
    k_tgemm<false, false, false><<<grid1, 256, SMEM>>>(HC, 640, Wg, nullptr, nullptr, 0,
                                                       zb, 128, Nn, 128, 128);

    // CSR build (needed before k_gat)
    cudaMemsetAsync(degp, 0, Nn * sizeof(int));
    k_count<<<(Ee + 255) / 256, 256>>>(dst);
    const int nb = (Nn + 1023) / 1024;
    k_scan1<<<nb, 1024>>>();
    k_scan2<<<1, 128>>>(nb);
    k_finalize<<<(Nn + 255) / 256, 256>>>();
    k_fill<<<(Ee + 255) / 256, 256>>>(dst);

    for (int l = 0; l < 4; l++) {
        const float* h = HC + l * 128;
        if (l > 0) {
            k_tgemm<false, false, false><<<grid1, 256, SMEM>>>(h, 640, Wg + (size_t)l * 16384,
                                                               nullptr, nullptr, 0, zb, 128, Nn, 128, 128);
        }
        k_eler<<<(Nn * 16 + 255) / 256, 256>>>(zb, gat_al + l * 128, gat_ar + l * 128);
        k_gat<<<warpBlocks, 256>>>(zb, src, h, 640, gat_b + l * 128, yb);
        // BN1
        cudaMemsetAsync(bns, 0, 256 * sizeof(float));
        k_bn_stats<<<512, 128>>>(yb);
        k_bn_apply<<<bnApplyBlocks, 256>>>(yb, bn1_g + l * 128, bn1_b + l * 128, hm, 128);
        // FF
        k_tgemm<true, true, false><<<grid2, 256, SMEM>>>(hm, 128, Wf1 + (size_t)l * 32768,
                                                         ff_b1 + l * 256, nullptr, 0, tb, 256, Nn, 128, 256);
        k_tgemm<false, true, true><<<grid1, 256, SMEM>>>(tb, 256, Wf2 + (size_t)l * 32768,
                                                         ff_b2 + l * 128, hm, 128, yb, 128, Nn, 256, 128);
        // BN2 -> next column block of HC
        cudaMemsetAsync(bns, 0, 256 * sizeof(float));
        k_bn_stats<<<512, 128>>>(yb);
        k_bn_apply<<<bnApplyBlocks, 256>>>(yb, bn2_g + l * 128, bn2_b + l * 128,
                                           HC + (size_t)(l + 1) * 128, 640);
    }

    // decoder
    k_tgemm<true, true, false><<<grid1, 256, SMEM>>>(HC, 640, Wd, dec_b1, nullptr, 0,
                                                     tb, 128, Nn, 640, 128);
    k_dec_out<<<warpBlocks, 256>>>(tb, dec_W2, dec_b2, (float*)d_out);
}

// round 5
// speedup vs baseline: 2.0844x; 1.3338x over previous
#include <cuda_runtime.h>
#include <cstdint>

#define Nn 100000
#define Ee 600000
#define EPSBN 1e-5f
#define SLOPE 0.2f

// ---------------- scratch (device globals; no allocs allowed) ----------------
__device__ float g_HC[(size_t)Nn * 640];
__device__ float g_z[(size_t)Nn * 128];
__device__ float g_t[(size_t)Nn * 256];
__device__ float g_y[(size_t)Nn * 128];
__device__ float g_hmid[(size_t)Nn * 128];
__device__ float g_el[(size_t)Nn * 16];
__device__ float g_er[(size_t)Nn * 16];
__device__ float g_bnsum[8 * 256];   // 8 BN instances: [sum(128) | sumsq(128)]
__device__ int   g_deg[Nn];
__device__ int   g_scan[Nn];
__device__ int   g_bsum[128];
__device__ int   g_rowptr[Nn + 1];
__device__ int   g_cursor[Nn];
__device__ int   g_eid[Ee];
// tf32 weights: gat[65536] ff1[131072] ff2[131072] dec[81920] embW2[16384]
__device__ float g_W[425984];

__device__ __forceinline__ float to_tf32(float x) {
    float r;
    asm("cvt.rna.tf32.f32 %0, %1;" : "=f"(r) : "f"(x));
    return r;
}
__device__ __forceinline__ uint32_t smem_to_u32(const void* p) {
    uint32_t a;
    asm("{ .reg .u64 t; cvta.to.shared.u64 t, %1; cvt.u32.u64 %0, t; }" : "=r"(a) : "l"(p));
    return a;
}
__device__ __forceinline__ void cp16(uint32_t dst, const void* src, bool ok) {
    int sz = ok ? 16 : 0;
    asm volatile("cp.async.cg.shared.global [%0], [%1], 16, %2;"
                 :: "r"(dst), "l"(src), "r"(sz) : "memory");
}
#define CP_COMMIT() asm volatile("cp.async.commit_group;" ::: "memory")
#define CP_WAIT2() asm volatile("cp.async.wait_group 2;" ::: "memory")

#define MMA_TF32(d, av, bv)                                               \
    asm volatile(                                                         \
        "mma.sync.aligned.m16n8k8.row.col.f32.tf32.tf32.f32 "             \
        "{%0,%1,%2,%3},{%4,%5,%6,%7},{%8,%9},{%0,%1,%2,%3};"              \
        : "+f"((d)[0]), "+f"((d)[1]), "+f"((d)[2]), "+f"((d)[3])          \
        : "r"((av)[0]), "r"((av)[1]), "r"((av)[2]), "r"((av)[3]),         \
          "r"((bv)[0]), "r"((bv)[1]))

// ---------------- CSR build ----------------
__global__ void k_count(const int* __restrict__ dst) {
    int e = blockIdx.x * blockDim.x + threadIdx.x;
    if (e < Ee) atomicAdd(&g_deg[dst[e]], 1);
}
__global__ void k_scan1() {
    __shared__ int s[1024];
    int i = blockIdx.x * 1024 + threadIdx.x;
    int v = (i < Nn) ? g_deg[i] : 0;
    s[threadIdx.x] = v;
    __syncthreads();
    for (int off = 1; off < 1024; off <<= 1) {
        int t = (threadIdx.x >= off) ? s[threadIdx.x - off] : 0;
        __syncthreads();
        s[threadIdx.x] += t;
        __syncthreads();
    }
    if (i < Nn) g_scan[i] = s[threadIdx.x];
    if (threadIdx.x == 1023) g_bsum[blockIdx.x] = s[1023];
}
__global__ void k_scan2(int nb) {
    __shared__ int s[128];
    int v = (threadIdx.x < nb) ? g_bsum[threadIdx.x] : 0;
    s[threadIdx.x] = v;
    __syncthreads();
    for (int off = 1; off < 128; off <<= 1) {
        int t = (threadIdx.x >= off) ? s[threadIdx.x - off] : 0;
        __syncthreads();
        s[threadIdx.x] += t;
        __syncthreads();
    }
    g_bsum[threadIdx.x] = (threadIdx.x == 0) ? 0 : s[threadIdx.x - 1];
}
__global__ void k_finalize() {
    int i = blockIdx.x * blockDim.x + threadIdx.x;
    if (i >= Nn) return;
    int incl = g_scan[i] + g_bsum[i >> 10];
    g_rowptr[i + 1] = incl;
    g_cursor[i] = incl - g_deg[i];
    if (i == 0) g_rowptr[0] = 0;
}
__global__ void k_fill(const int* __restrict__ dst) {
    int e = blockIdx.x * blockDim.x + threadIdx.x;
    if (e < Ee) {
        int d = dst[e];
        int p = atomicAdd(&g_cursor[d], 1);
        g_eid[p] = e;
    }
}

// ---------------- all-weight cvt (rna tf32) ----------------
__global__ void k_cvt_all(const float* __restrict__ gat_W, const float* __restrict__ ff_W1,
                          const float* __restrict__ ff_W2, const float* __restrict__ dec_W1,
                          const float* __restrict__ emb_W2) {
    int i = blockIdx.x * blockDim.x + threadIdx.x;
    if (i >= 425984) return;
    float v;
    if (i < 65536) v = gat_W[i];
    else if (i < 196608) v = ff_W1[i - 65536];
    else if (i < 327680) v = ff_W2[i - 196608];
    else if (i < 409600) v = dec_W1[i - 327680];
    else v = emb_W2[i - 409600];
    g_W[i] = to_tf32(v);
}

// ---------------- embed stage 1: t = relu(x@W1+b1), res = x@Ws+bs+b2 ----------------
__global__ void k_embed1(const float* __restrict__ x,
                         const float* __restrict__ W1, const float* __restrict__ b1,
                         const float* __restrict__ b2,
                         const float* __restrict__ Ws, const float* __restrict__ bs) {
    int idx = blockIdx.x * blockDim.x + threadIdx.x;
    if (idx >= Nn * 128) return;
    int n = idx >> 7, c = idx & 127;
    float x0 = x[n * 2], x1 = x[n * 2 + 1];
    float tv = fmaf(x0, W1[c], fmaf(x1, W1[128 + c], b1[c]));
    g_t[idx] = tv > 0.f ? tv : 0.f;
    g_y[idx] = fmaf(x0, Ws[c], fmaf(x1, Ws[128 + c], bs[c] + b2[c]));
}

// ---------------- tf32 tensor GEMM, cp.async 4-stage pipeline ----------------
// C = A[N,Mred] @ B[Mred,Kcols] (+bias)(relu)(+res)(+BN stats). B pre-rounded tf32,
// A rounded rna in-register. BM=128, BN=128, BK=16, 256 thr, warp tile 32x64.
template <bool RELU, bool HAS_BIAS, bool HAS_RES, bool DO_BN>
__global__ void __launch_bounds__(256) k_tgemm(
    const float* __restrict__ A, int lda,
    const float* __restrict__ B,
    const float* __restrict__ bias,
    const float* __restrict__ Res, int ldres,
    float* __restrict__ C, int ldc,
    int Nrows, int Mred, int Kcols, float* bnslot) {
    constexpr int S = 4;
    constexpr int ASTG = 128 * 20;
    constexpr int BSTG = 16 * 136;
    extern __shared__ float sm[];
    float* AsF = sm;
    float* BsF = sm + S * ASTG;

    const int tid = threadIdx.x;
    const int lane = tid & 31;
    const int wid = tid >> 5;
    const int bm = blockIdx.x * 128;
    const int bn = blockIdx.y * 128;

    const int m0 = (wid & 3) * 32;
    const int n0 = (wid >> 2) * 64;
    const int qrow = lane >> 2;
    const int qk = lane & 3;

    const int arow = tid >> 1;
    const int aseg = (tid & 1) * 8;
    const int brow = tid >> 4;
    const int bcol = (tid & 15) * 8;

    const int gr = bm + arow;
    const bool aok = gr < Nrows;
    const float* Asrc = A + (size_t)gr * lda + aseg;
    const float* Bsrc = B + (size_t)brow * Kcols + bn + bcol;
    const uint32_t adst = smem_to_u32(AsF) + (uint32_t)(arow * 20 + aseg) * 4u;
    const uint32_t bdst = smem_to_u32(BsF) + (uint32_t)(brow * 136 + bcol) * 4u;

    float acc[2][8][4];
#pragma unroll
    for (int mi = 0; mi < 2; mi++)
#pragma unroll
        for (int ni = 0; ni < 8; ni++)
#pragma unroll
            for (int j = 0; j < 4; j++) acc[mi][ni][j] = 0.f;

    const int nIter = Mred >> 4;

#pragma unroll
    for (int s = 0; s < S - 1; s++) {
        if (s < nIter) {
            int kt = s << 4;
            cp16(adst + (uint32_t)(s * ASTG) * 4u, Asrc + kt, aok);
            cp16(adst + (uint32_t)(s * ASTG) * 4u + 16u, Asrc + kt + 4, aok);
            cp16(bdst + (uint32_t)(s * BSTG) * 4u, Bsrc + (size_t)kt * Kcols, true);
            cp16(bdst + (uint32_t)(s * BSTG) * 4u + 16u, Bsrc + (size_t)kt * Kcols + 4, true);
        }
        CP_COMMIT();
    }

    for (int it = 0; it < nIter; it++) {
        CP_WAIT2();
        __syncthreads();

        const int stg = it & (S - 1);
        const float* as = AsF + stg * ASTG;
        const float* bs = BsF + stg * BSTG;
#pragma unroll
        for (int ks = 0; ks < 2; ks++) {
            const int kbase = ks * 8;
            uint32_t a[2][4];
#pragma unroll
            for (int mi = 0; mi < 2; mi++) {
                const float* ap = as + (m0 + mi * 16 + qrow) * 20 + kbase + qk;
                a[mi][0] = __float_as_uint(to_tf32(ap[0]));
                a[mi][1] = __float_as_uint(to_tf32(ap[8 * 20]));
                a[mi][2] = __float_as_uint(to_tf32(ap[4]));
                a[mi][3] = __float_as_uint(to_tf32(ap[8 * 20 + 4]));
            }
            uint32_t b[8][2];
#pragma unroll
            for (int ni = 0; ni < 8; ni++) {
                const float* bp = bs + (kbase + qk) * 136 + n0 + ni * 8 + qrow;
                b[ni][0] = __float_as_uint(bp[0]);
                b[ni][1] = __float_as_uint(bp[4 * 136]);
            }
#pragma unroll
            for (int mi = 0; mi < 2; mi++)
#pragma unroll
                for (int ni = 0; ni < 8; ni++) MMA_TF32(acc[mi][ni], a[mi], b[ni]);
        }
        __syncthreads();

        const int nx = it + S - 1;
        if (nx < nIter) {
            const int s = nx & (S - 1);
            const int kt = nx << 4;
            cp16(adst + (uint32_t)(s * ASTG) * 4u, Asrc + kt, aok);
            cp16(adst + (uint32_t)(s * ASTG) * 4u + 16u, Asrc + kt + 4, aok);
            cp16(bdst + (uint32_t)(s * BSTG) * 4u, Bsrc + (size_t)kt * Kcols, true);
            cp16(bdst + (uint32_t)(s * BSTG) * 4u + 16u, Bsrc + (size_t)kt * Kcols + 4, true);
        }
        CP_COMMIT();
    }

    // epilogue
    float s0[8], s1[8], q0[8], q1[8];
    if (DO_BN) {
#pragma unroll
        for (int ni = 0; ni < 8; ni++) { s0[ni] = 0.f; s1[ni] = 0.f; q0[ni] = 0.f; q1[ni] = 0.f; }
    }
#pragma unroll
    for (int mi = 0; mi < 2; mi++) {
#pragma unroll
        for (int half = 0; half < 2; half++) {
            int r = bm + m0 + mi * 16 + qrow + half * 8;
            bool rok = r < Nrows;
#pragma unroll
            for (int ni = 0; ni < 8; ni++) {
                int gc = bn + n0 + ni * 8 + qk * 2;
                float v0 = acc[mi][ni][half * 2 + 0];
                float v1 = acc[mi][ni][half * 2 + 1];
                if (HAS_BIAS) {
                    v0 += bias[gc];
                    v1 += bias[gc + 1];
                }
                if (RELU) {
                    v0 = fmaxf(v0, 0.f);
                    v1 = fmaxf(v1, 0.f);
                }
                if (HAS_RES && rok) {
                    const float* rp = Res + (size_t)r * ldres + gc;
                    v0 += rp[0];
                    v1 += rp[1];
                }
                if (rok) *(float2*)(C + (size_t)r * ldc + gc) = make_float2(v0, v1);
                if (DO_BN && rok) {
                    s0[ni] += v0; q0[ni] += v0 * v0;
                    s1[ni] += v1; q1[ni] += v1 * v1;
                }
            }
        }
    }

    if (DO_BN) {
        // reduce over qrow lanes (same qk share identical channels)
#pragma unroll
        for (int ni = 0; ni < 8; ni++) {
            s0[ni] += __shfl_xor_sync(0xffffffffu, s0[ni], 4);
            s0[ni] += __shfl_xor_sync(0xffffffffu, s0[ni], 8);
            s0[ni] += __shfl_xor_sync(0xffffffffu, s0[ni], 16);
            s1[ni] += __shfl_xor_sync(0xffffffffu, s1[ni], 4);
            s1[ni] += __shfl_xor_sync(0xffffffffu, s1[ni], 8);
            s1[ni] += __shfl_xor_sync(0xffffffffu, s1[ni], 16);
            q0[ni] += __shfl_xor_sync(0xffffffffu, q0[ni], 4);
            q0[ni] += __shfl_xor_sync(0xffffffffu, q0[ni], 8);
            q0[ni] += __shfl_xor_sync(0xffffffffu, q0[ni], 16);
            q1[ni] += __shfl_xor_sync(0xffffffffu, q1[ni], 4);
            q1[ni] += __shfl_xor_sync(0xffffffffu, q1[ni], 8);
            q1[ni] += __shfl_xor_sync(0xffffffffu, q1[ni], 16);
        }
        __syncthreads();
        if (lane < 4) {  // qrow == 0 lanes; qk == lane
            int mg = wid & 3;
#pragma unroll
            for (int ni = 0; ni < 8; ni++) {
                int c = n0 + ni * 8 + lane * 2;
                sm[mg * 128 + c] = s0[ni];
                sm[mg * 128 + c + 1] = s1[ni];
                sm[512 + mg * 128 + c] = q0[ni];
                sm[512 + mg * 128 + c + 1] = q1[ni];
            }
        }
        __syncthreads();
        {
            int c = tid & 127, st = tid >> 7;
            float v = sm[st * 512 + c] + sm[st * 512 + 128 + c] +
                      sm[st * 512 + 256 + c] + sm[st * 512 + 384 + c];
            atomicAdd(bnslot + st * 128 + c, v);
        }
    }
}

// ---------------- el / er ----------------
__global__ void k_eler(const float* __restrict__ z, const float* __restrict__ al,
                       const float* __restrict__ ar) {
    int t = blockIdx.x * blockDim.x + threadIdx.x;
    if (t >= Nn * 16) return;
    int n = t >> 4, h = t & 15;
    const float* zr = z + (size_t)n * 128 + h * 8;
    const float* a = al + h * 8;
    const float* r = ar + h * 8;
    float sl = 0.f, sr = 0.f;
#pragma unroll
    for (int d = 0; d < 8; d++) {
        float zv = zr[d];
        sl += zv * a[d];
        sr += zv * r[d];
    }
    g_el[t] = sl;
    g_er[t] = sr;
}

// ---------------- GAT aggregate (warp per node) + fused BN1 stats ----------------
__global__ void k_gat(const float* __restrict__ z, const int* __restrict__ src,
                      const float* __restrict__ hres, int ldh,
                      const float* __restrict__ bias, float* __restrict__ y,
                      float* __restrict__ bnslot) {
    __shared__ float sbn[2][8][128];
    int gw = (blockIdx.x * blockDim.x + threadIdx.x) >> 5;
    int lane = threadIdx.x & 31;
    int wid = threadIdx.x >> 5;
    float4 o = make_float4(0.f, 0.f, 0.f, 0.f);
    if (gw < Nn) {
        int head = lane >> 1;
        int beg = g_rowptr[gw], end = g_rowptr[gw + 1];
        float er_h = g_er[gw * 16 + head];

        float m = -1e30f;
        for (int i = beg; i < end; i++) {
            int s = src[g_eid[i]];
            float v = g_el[s * 16 + head] + er_h;
            v = v > 0.f ? v : SLOPE * v;
            m = fmaxf(m, v);
        }
        float den = 0.f;
        float4 acc = make_float4(0.f, 0.f, 0.f, 0.f);
        const float4* z4 = (const float4*)z;
        for (int i = beg; i < end; i++) {
            int s = src[g_eid[i]];
            float v = g_el[s * 16 + head] + er_h;
            v = v > 0.f ? v : SLOPE * v;
            float w = expf(v - m);
            den += w;
            float4 zv = z4[(size_t)s * 32 + lane];
            acc.x += w * zv.x; acc.y += w * zv.y; acc.z += w * zv.z; acc.w += w * zv.w;
        }
        float dinv = den > 0.f ? 1.f / den : 1.f;
        float4 b4 = ((const float4*)bias)[lane];
        float4 h4 = *(const float4*)(hres + (size_t)gw * ldh + lane * 4);
        o.x = acc.x * dinv + b4.x + h4.x;
        o.y = acc.y * dinv + b4.y + h4.y;
        o.z = acc.z * dinv + b4.z + h4.z;
        o.w = acc.w * dinv + b4.w + h4.w;
        ((float4*)y)[(size_t)gw * 32 + lane] = o;
    }
    ((float4*)sbn[0][wid])[lane] = o;
    ((float4*)sbn[1][wid])[lane] = make_float4(o.x * o.x, o.y * o.y, o.z * o.z, o.w * o.w);
    __syncthreads();
    int c = threadIdx.x & 127, st = threadIdx.x >> 7;
    float v = 0.f;
#pragma unroll
    for (int w = 0; w < 8; w++) v += sbn[st][w][c];
    atomicAdd(bnslot + st * 128 + c, v);
}

// ---------------- BatchNorm apply (vectorized) ----------------
__global__ void k_bn_apply(const float* __restrict__ y, const float* __restrict__ g,
                           const float* __restrict__ b, float* __restrict__ out, int ldo,
                           const float* __restrict__ slot) {
    int idx = blockIdx.x * blockDim.x + threadIdx.x;
    if (idx >= Nn * 32) return;
    int n = idx >> 5, c4 = idx & 31;
    int c = c4 * 4;
    const float invN = 1.f / (float)Nn;
    float4 v = ((const float4*)y)[idx];
    float4 ov;
    {
        float mu = slot[c] * invN;
        float var = slot[128 + c] * invN - mu * mu;
        ov.x = (v.x - mu) * rsqrtf(var + EPSBN) * g[c] + b[c];
    }
    {
        float mu = slot[c + 1] * invN;
        float var = slot[128 + c + 1] * invN - mu * mu;
        ov.y = (v.y - mu) * rsqrtf(var + EPSBN) * g[c + 1] + b[c + 1];
    }
    {
        float mu = slot[c + 2] * invN;
        float var = slot[128 + c + 2] * invN - mu * mu;
        ov.z = (v.z - mu) * rsqrtf(var + EPSBN) * g[c + 2] + b[c + 2];
    }
    {
        float mu = slot[c + 3] * invN;
        float var = slot[128 + c + 3] * invN - mu * mu;
        ov.w = (v.w - mu) * rsqrtf(var + EPSBN) * g[c + 3] + b[c + 3];
    }
    *(float4*)(out + (size_t)n * ldo + c) = ov;
}

// ---------------- decoder final dot ----------------
__global__ void k_dec_out(const float* __restrict__ t, const float* __restrict__ W2,
                          const float* __restrict__ b2, float* __restrict__ out) {
    int warp = (blockIdx.x * blockDim.x + threadIdx.x) >> 5;
    if (warp >= Nn) return;
    int lane = threadIdx.x & 31;
    float4 tv = ((const float4*)t)[(size_t)warp * 32 + lane];
    float4 wv = ((const float4*)W2)[lane];
    float s = tv.x * wv.x + tv.y * wv.y + tv.z * wv.z + tv.w * wv.w;
#pragma unroll
    for (int o = 16; o; o >>= 1) s += __shfl_down_sync(0xffffffffu, s, o);
    if (lane == 0) out[warp] = s + b2[0];
}

// ---------------- launch ----------------
extern "C" void kernel_launch(void* const* d_in, const int* in_sizes, int n_in,
                              void* d_out, int out_size) {
    const float* x      = (const float*)d_in[0];
    const int*   src    = (const int*)d_in[1];
    const int*   dst    = (const int*)d_in[2];
    const float* emb_W1 = (const float*)d_in[3];
    const float* emb_b1 = (const float*)d_in[4];
    const float* emb_W2 = (const float*)d_in[5];
    const float* emb_b2 = (const float*)d_in[6];
    const float* emb_Ws = (const float*)d_in[7];
    const float* emb_bs = (const float*)d_in[8];
    const float* gat_W  = (const float*)d_in[9];
    const float* gat_al = (const float*)d_in[10];
    const float* gat_ar = (const float*)d_in[11];
    const float* gat_b  = (const float*)d_in[12];
    const float* bn1_g  = (const float*)d_in[13];
    const float* bn1_b  = (const float*)d_in[14];
    const float* ff_W1  = (const float*)d_in[15];
    const float* ff_b1  = (const float*)d_in[16];
    const float* ff_W2  = (const float*)d_in[17];
    const float* ff_b2  = (const float*)d_in[18];
    const float* bn2_g  = (const float*)d_in[19];
    const float* bn2_b  = (const float*)d_in[20];
    const float* dec_W1 = (const float*)d_in[21];
    const float* dec_b1 = (const float*)d_in[22];
    const float* dec_W2 = (const float*)d_in[23];
    const float* dec_b2 = (const float*)d_in[24];

    void* p;
    float *HC, *zb, *tb, *yb, *hm, *bns, *W;
    int* degp;
    cudaGetSymbolAddress(&p, g_HC);    HC = (float*)p;
    cudaGetSymbolAddress(&p, g_z);     zb = (float*)p;
    cudaGetSymbolAddress(&p, g_t);     tb = (float*)p;
    cudaGetSymbolAddress(&p, g_y);     yb = (float*)p;
    cudaGetSymbolAddress(&p, g_hmid);  hm = (float*)p;
    cudaGetSymbolAddress(&p, g_bnsum); bns = (float*)p;
    cudaGetSymbolAddress(&p, g_deg);   degp = (int*)p;
    cudaGetSymbolAddress(&p, g_W);     W = (float*)p;

    float* Wg = W;            // [4][128,128]
    float* Wf1 = W + 65536;   // [4][128,256]
    float* Wf2 = W + 196608;  // [4][256,128]
    float* Wd = W + 327680;   // [640,128]
    float* We2 = W + 409600;  // [128,128]

    const int SMEM = (4 * 128 * 20 + 4 * 16 * 136) * 4;  // 75776 B
    static bool attrDone = false;
    if (!attrDone) {
        cudaFuncSetAttribute(k_tgemm<false, false, false, false>, cudaFuncAttributeMaxDynamicSharedMemorySize, SMEM);
        cudaFuncSetAttribute(k_tgemm<true, true, false, false>, cudaFuncAttributeMaxDynamicSharedMemorySize, SMEM);
        cudaFuncSetAttribute(k_tgemm<false, true, true, true>, cudaFuncAttributeMaxDynamicSharedMemorySize, SMEM);
        cudaFuncSetAttribute(k_tgemm<false, false, true, false>, cudaFuncAttributeMaxDynamicSharedMemorySize, SMEM);
        attrDone = true;
    }

    cudaMemsetAsync(bns, 0, 8 * 256 * sizeof(float));
    cudaMemsetAsync(degp, 0, Nn * sizeof(int));

    // kernel 1: all-weight cvt
    k_cvt_all<<<(425984 + 255) / 256, 256>>>(gat_W, ff_W1, ff_W2, dec_W1, emb_W2);
    // kernel 2: embed stage 1
    k_embed1<<<(Nn * 128 + 255) / 256, 256>>>(x, emb_W1, emb_b1, emb_b2, emb_Ws, emb_bs);
    // kernel 3: CSR count
    k_count<<<(Ee + 255) / 256, 256>>>(dst);

    const int gx = (Nn + 127) / 128;  // 782
    dim3 grid1(gx, 1), grid2(gx, 2);
    const int bnBlocks = (Nn * 32 + 255) / 256;
    const int warpBlocks = (Nn * 32 + 255) / 256;

    // kernel 4: embed stage 2 GEMM (ncu profiling target)
    k_tgemm<false, false, true, false><<<grid1, 256, SMEM>>>(tb, 128, We2, nullptr, yb, 128,
                                                             HC, 640, Nn, 128, 128, nullptr);

    // kernels 5-8: CSR finish
    const int nb = (Nn + 1023) / 1024;
    k_scan1<<<nb, 1024>>>();
    k_scan2<<<1, 128>>>(nb);
    k_finalize<<<(Nn + 255) / 256, 256>>>();
    k_fill<<<(Ee + 255) / 256, 256>>>(dst);

    for (int l = 0; l < 4; l++) {
        const float* h = HC + l * 128;
        float* slot1 = bns + (2 * l) * 256;
        float* slot2 = bns + (2 * l + 1) * 256;
        // z = h @ gat_W[l]
        k_tgemm<false, false, false, false><<<grid1, 256, SMEM>>>(h, 640, Wg + (size_t)l * 16384,
                                                                  nullptr, nullptr, 0, zb, 128,
                                                                  Nn, 128, 128, nullptr);
        k_eler<<<(Nn * 16 + 255) / 256, 256>>>(zb, gat_al + l * 128, gat_ar + l * 128);
        k_gat<<<warpBlocks, 256>>>(zb, src, h, 640, gat_b + l * 128, yb, slot1);
        k_bn_apply<<<bnBlocks, 256>>>(yb, bn1_g + l * 128, bn1_b + l * 128, hm, 128, slot1);
        // FF
        k_tgemm<true, true, false, false><<<grid2, 256, SMEM>>>(hm, 128, Wf1 + (size_t)l * 32768,
                                                                ff_b1 + l * 256, nullptr, 0, tb, 256,
                                                                Nn, 128, 256, nullptr);
        k_tgemm<false, true, true, true><<<grid1, 256, SMEM>>>(tb, 256, Wf2 + (size_t)l * 32768,
                                                               ff_b2 + l * 128, hm, 128, yb, 128,
                                                               Nn, 256, 128, slot2);
        k_bn_apply<<<bnBlocks, 256>>>(yb, bn2_g + l * 128, bn2_b + l * 128,
                                      HC + (size_t)(l + 1) * 128, 640, slot2);
    }

    // decoder
    k_tgemm<true, true, false, false><<<grid1, 256, SMEM>>>(HC, 640, Wd, dec_b1, nullptr, 0,
                                                            tb, 128, Nn, 640, 128, nullptr);
    k_dec_out<<<warpBlocks, 256>>>(tb, dec_W2, dec_b2, (float*)d_out);
}

// round 6
// speedup vs baseline: 2.4628x; 1.1815x over previous
#include <cuda_runtime.h>
#include <cstdint>

#define Nn 100000
#define Ee 600000
#define EPSBN 1e-5f
#define SLOPE 0.2f

// ---------------- scratch (device globals; no allocs allowed) ----------------
__device__ float g_HC[(size_t)Nn * 640];   // raw (pre-BN) column blocks
__device__ float g_z[(size_t)Nn * 128];
__device__ float g_t[(size_t)Nn * 256];
__device__ float g_y[(size_t)Nn * 128];
__device__ float g_el[(size_t)Nn * 16];
__device__ float g_er[(size_t)Nn * 16];
__device__ float g_bnsum[8 * 256];  // 8 BN instances: [sum(128) | sumsq(128)]
__device__ int   g_deg[Nn];
__device__ int   g_scan[Nn];
__device__ int   g_bsum[128];
__device__ int   g_rowptr[Nn + 1];
__device__ int   g_cursor[Nn];
__device__ int   g_eid[Ee];
// tf32 weights: gat[65536] ff1[131072] ff2[131072] dec[81920] embW2[16384]
__device__ float g_W[425984];

__device__ __forceinline__ float to_tf32(float x) {
    float r;
    asm("cvt.rna.tf32.f32 %0, %1;" : "=f"(r) : "f"(x));
    return r;
}
__device__ __forceinline__ uint32_t smem_to_u32(const void* p) {
    uint32_t a;
    asm("{ .reg .u64 t; cvta.to.shared.u64 t, %1; cvt.u32.u64 %0, t; }" : "=r"(a) : "l"(p));
    return a;
}
__device__ __forceinline__ void cp16(uint32_t dst, const void* src, bool ok) {
    int sz = ok ? 16 : 0;
    asm volatile("cp.async.cg.shared.global [%0], [%1], 16, %2;"
                 :: "r"(dst), "l"(src), "r"(sz) : "memory");
}
#define CP_COMMIT() asm volatile("cp.async.commit_group;" ::: "memory")
#define CP_WAIT2() asm volatile("cp.async.wait_group 2;" ::: "memory")

#define MMA_TF32(d, av, bv)                                               \
    asm volatile(                                                         \
        "mma.sync.aligned.m16n8k8.row.col.f32.tf32.tf32.f32 "             \
        "{%0,%1,%2,%3},{%4,%5,%6,%7},{%8,%9},{%0,%1,%2,%3};"              \
        : "+f"((d)[0]), "+f"((d)[1]), "+f"((d)[2]), "+f"((d)[3])          \
        : "r"((av)[0]), "r"((av)[1]), "r"((av)[2]), "r"((av)[3]),         \
          "r"((bv)[0]), "r"((bv)[1]))

// ---------------- CSR build ----------------
__global__ void k_count(const int* __restrict__ dst) {
    int e = blockIdx.x * blockDim.x + threadIdx.x;
    if (e < Ee) atomicAdd(&g_deg[dst[e]], 1);
}
__global__ void k_scan1() {
    __shared__ int s[1024];
    int i = blockIdx.x * 1024 + threadIdx.x;
    int v = (i < Nn) ? g_deg[i] : 0;
    s[threadIdx.x] = v;
    __syncthreads();
    for (int off = 1; off < 1024; off <<= 1) {
        int t = (threadIdx.x >= off) ? s[threadIdx.x - off] : 0;
        __syncthreads();
        s[threadIdx.x] += t;
        __syncthreads();
    }
    if (i < Nn) g_scan[i] = s[threadIdx.x];
    if (threadIdx.x == 1023) g_bsum[blockIdx.x] = s[1023];
}
__global__ void k_scan2(int nb) {
    __shared__ int s[128];
    int v = (threadIdx.x < nb) ? g_bsum[threadIdx.x] : 0;
    s[threadIdx.x] = v;
    __syncthreads();
    for (int off = 1; off < 128; off <<= 1) {
        int t = (threadIdx.x >= off) ? s[threadIdx.x - off] : 0;
        __syncthreads();
        s[threadIdx.x] += t;
        __syncthreads();
    }
    g_bsum[threadIdx.x] = (threadIdx.x == 0) ? 0 : s[threadIdx.x - 1];
}
__global__ void k_finalize() {
    int i = blockIdx.x * blockDim.x + threadIdx.x;
    if (i >= Nn) return;
    int incl = g_scan[i] + g_bsum[i >> 10];
    g_rowptr[i + 1] = incl;
    g_cursor[i] = incl - g_deg[i];
    if (i == 0) g_rowptr[0] = 0;
}
__global__ void k_fill(const int* __restrict__ dst) {
    int e = blockIdx.x * blockDim.x + threadIdx.x;
    if (e < Ee) {
        int d = dst[e];
        int p = atomicAdd(&g_cursor[d], 1);
        g_eid[p] = e;
    }
}

// ---------------- all-weight cvt (rna tf32) ----------------
__global__ void k_cvt_all(const float* __restrict__ gat_W, const float* __restrict__ ff_W1,
                          const float* __restrict__ ff_W2, const float* __restrict__ dec_W1,
                          const float* __restrict__ emb_W2) {
    int i = blockIdx.x * blockDim.x + threadIdx.x;
    if (i >= 425984) return;
    float v;
    if (i < 65536) v = gat_W[i];
    else if (i < 196608) v = ff_W1[i - 65536];
    else if (i < 327680) v = ff_W2[i - 196608];
    else if (i < 409600) v = dec_W1[i - 327680];
    else v = emb_W2[i - 409600];
    g_W[i] = to_tf32(v);
}

// ---------------- embed stage 1 ----------------
__global__ void k_embed1(const float* __restrict__ x,
                         const float* __restrict__ W1, const float* __restrict__ b1,
                         const float* __restrict__ b2,
                         const float* __restrict__ Ws, const float* __restrict__ bs) {
    int idx = blockIdx.x * blockDim.x + threadIdx.x;
    if (idx >= Nn * 128) return;
    int n = idx >> 7, c = idx & 127;
    float x0 = x[n * 2], x1 = x[n * 2 + 1];
    float tv = fmaf(x0, W1[c], fmaf(x1, W1[128 + c], b1[c]));
    g_t[idx] = tv > 0.f ? tv : 0.f;
    g_y[idx] = fmaf(x0, Ws[c], fmaf(x1, Ws[128 + c], bs[c] + b2[c]));
}

// ---------------- fused tf32 tensor GEMM ----------------
// C = affA(A)[N,Mred] @ B[Mred,Kcols] (+bias)(relu)(+affR(Res))(+BN stats)(+el/er)
// AAFF: 0 none, 1 single slot, 2 decoder concat (identity block0 + 4 BN2 slots).
template <int RELU, int BIAS, int RES, int BN, int ELER, int AAFF, int RAFF>
__global__ void __launch_bounds__(256) k_tgemm(
    const float* __restrict__ A, int lda,
    const float* __restrict__ B,
    const float* __restrict__ bias,
    const float* __restrict__ Res, int ldres,
    float* __restrict__ C, int ldc,
    int Nrows, int Mred, int Kcols, float* bnslot,
    const float* affA, const float* affAg, const float* affAb,
    const float* affR, const float* affRg, const float* affRb,
    const float* al, const float* ar) {
    constexpr int S = 4;
    constexpr int ASTG = 128 * 20;
    constexpr int BSTG = 16 * 136;
    constexpr int STGF = S * ASTG + S * BSTG;  // 18944
    constexpr int SCA = STGF, SHA = SCA + 640, SCR = SHA + 640, SHR = SCR + 128;
    constexpr int ALO = SHR + 128, ARO = ALO + 128;
    extern __shared__ float sm[];
    float* AsF = sm;
    float* BsF = sm + S * ASTG;

    const int tid = threadIdx.x;
    const int lane = tid & 31;
    const int wid = tid >> 5;
    const int bm = blockIdx.x * 128;
    const int bn = blockIdx.y * 128;

    const int m0 = (wid & 3) * 32;
    const int n0 = (wid >> 2) * 64;
    const int qrow = lane >> 2;
    const int qk = lane & 3;

    const int arow = tid >> 1;
    const int aseg = (tid & 1) * 8;
    const int brow = tid >> 4;
    const int bcol = (tid & 15) * 8;

    const int gr = bm + arow;
    const bool aok = gr < Nrows;
    const float* Asrc = A + (size_t)gr * lda + aseg;
    const float* Bsrc = B + (size_t)brow * Kcols + bn + bcol;
    const uint32_t adst = smem_to_u32(AsF) + (uint32_t)(arow * 20 + aseg) * 4u;
    const uint32_t bdst = smem_to_u32(BsF) + (uint32_t)(brow * 136 + bcol) * 4u;

    const int nIter = Mred >> 4;

    // issue prologue stages first so affine build overlaps the loads
#pragma unroll
    for (int s = 0; s < S - 1; s++) {
        if (s < nIter) {
            int kt = s << 4;
            cp16(adst + (uint32_t)(s * ASTG) * 4u, Asrc + kt, aok);
            cp16(adst + (uint32_t)(s * ASTG) * 4u + 16u, Asrc + kt + 4, aok);
            cp16(bdst + (uint32_t)(s * BSTG) * 4u, Bsrc + (size_t)kt * Kcols, true);
            cp16(bdst + (uint32_t)(s * BSTG) * 4u + 16u, Bsrc + (size_t)kt * Kcols + 4, true);
        }
        CP_COMMIT();
    }

    const float invN = 1.f / (float)Nn;
    if (AAFF) {
        for (int k = tid; k < Mred; k += 256) {
            float scv = 1.f, shv = 0.f;
            const float *slot = nullptr, *gg = nullptr, *bb = nullptr;
            int c = k;
            if (AAFF == 1) { slot = affA; gg = affAg; bb = affAb; }
            else {
                int blk = k >> 7;
                c = k & 127;
                if (blk > 0) {
                    slot = g_bnsum + (size_t)(2 * (blk - 1) + 1) * 256;
                    gg = affAg + (blk - 1) * 128;
                    bb = affAb + (blk - 1) * 128;
                }
            }
            if (slot) {
                float mu = slot[c] * invN;
                float var = slot[c + 128] * invN - mu * mu;
                float rs = rsqrtf(var + EPSBN);
                scv = gg[c] * rs;
                shv = bb[c] - mu * scv;
            }
            sm[SCA + k] = scv;
            sm[SHA + k] = shv;
        }
    }
    if (RAFF) {
        if (tid < 128) {
            float mu = affR[tid] * invN;
            float var = affR[tid + 128] * invN - mu * mu;
            float rs = rsqrtf(var + EPSBN);
            float scv = affRg[tid] * rs;
            sm[SCR + tid] = scv;
            sm[SHR + tid] = affRb[tid] - mu * scv;
        }
    }
    if (ELER) {
        if (tid < 128) sm[ALO + tid] = al[tid];
        else if (tid < 256) sm[ARO + tid - 128] = ar[tid - 128];
    }

    float acc[2][8][4];
#pragma unroll
    for (int mi = 0; mi < 2; mi++)
#pragma unroll
        for (int ni = 0; ni < 8; ni++)
#pragma unroll
            for (int j = 0; j < 4; j++) acc[mi][ni][j] = 0.f;

    for (int it = 0; it < nIter; it++) {
        CP_WAIT2();
        __syncthreads();

        const int stg = it & (S - 1);
        const float* as = AsF + stg * ASTG;
        const float* bs = BsF + stg * BSTG;
#pragma unroll
        for (int ks = 0; ks < 2; ks++) {
            const int kbase = ks * 8;
            float sc0 = 1.f, sc1 = 1.f, sh0 = 0.f, sh1 = 0.f;
            if (AAFF) {
                int kg = (it << 4) + kbase + qk;
                sc0 = sm[SCA + kg]; sh0 = sm[SHA + kg];
                sc1 = sm[SCA + kg + 4]; sh1 = sm[SHA + kg + 4];
            }
            uint32_t a[2][4];
#pragma unroll
            for (int mi = 0; mi < 2; mi++) {
                const float* ap = as + (m0 + mi * 16 + qrow) * 20 + kbase + qk;
                if (AAFF) {
                    a[mi][0] = __float_as_uint(to_tf32(fmaf(ap[0], sc0, sh0)));
                    a[mi][1] = __float_as_uint(to_tf32(fmaf(ap[8 * 20], sc0, sh0)));
                    a[mi][2] = __float_as_uint(to_tf32(fmaf(ap[4], sc1, sh1)));
                    a[mi][3] = __float_as_uint(to_tf32(fmaf(ap[8 * 20 + 4], sc1, sh1)));
                } else {
                    a[mi][0] = __float_as_uint(to_tf32(ap[0]));
                    a[mi][1] = __float_as_uint(to_tf32(ap[8 * 20]));
                    a[mi][2] = __float_as_uint(to_tf32(ap[4]));
                    a[mi][3] = __float_as_uint(to_tf32(ap[8 * 20 + 4]));
                }
            }
            uint32_t b[8][2];
#pragma unroll
            for (int ni = 0; ni < 8; ni++) {
                const float* bp = bs + (kbase + qk) * 136 + n0 + ni * 8 + qrow;
                b[ni][0] = __float_as_uint(bp[0]);
                b[ni][1] = __float_as_uint(bp[4 * 136]);
            }
#pragma unroll
            for (int mi = 0; mi < 2; mi++)
#pragma unroll
                for (int ni = 0; ni < 8; ni++) MMA_TF32(acc[mi][ni], a[mi], b[ni]);
        }

        const int nx = it + S - 1;
        if (nx < nIter) {
            const int s = nx & (S - 1);
            const int kt = nx << 4;
            cp16(adst + (uint32_t)(s * ASTG) * 4u, Asrc + kt, aok);
            cp16(adst + (uint32_t)(s * ASTG) * 4u + 16u, Asrc + kt + 4, aok);
            cp16(bdst + (uint32_t)(s * BSTG) * 4u, Bsrc + (size_t)kt * Kcols, true);
            cp16(bdst + (uint32_t)(s * BSTG) * 4u + 16u, Bsrc + (size_t)kt * Kcols + 4, true);
        }
        CP_COMMIT();
    }

    // epilogue
    float s0[8], s1[8], q0[8], q1[8];
    if (BN) {
#pragma unroll
        for (int ni = 0; ni < 8; ni++) { s0[ni] = 0.f; s1[ni] = 0.f; q0[ni] = 0.f; q1[ni] = 0.f; }
    }
#pragma unroll
    for (int mi = 0; mi < 2; mi++) {
#pragma unroll
        for (int half = 0; half < 2; half++) {
            int r = bm + m0 + mi * 16 + qrow + half * 8;
            bool rok = r < Nrows;
#pragma unroll
            for (int ni = 0; ni < 8; ni++) {
                int gc = bn + n0 + ni * 8 + qk * 2;
                float v0 = acc[mi][ni][half * 2 + 0];
                float v1 = acc[mi][ni][half * 2 + 1];
                if (BIAS) {
                    v0 += bias[gc];
                    v1 += bias[gc + 1];
                }
                if (RELU) {
                    v0 = fmaxf(v0, 0.f);
                    v1 = fmaxf(v1, 0.f);
                }
                if (RES && rok) {
                    const float* rp = Res + (size_t)r * ldres + gc;
                    float rv0 = rp[0], rv1 = rp[1];
                    if (RAFF) {
                        rv0 = fmaf(rv0, sm[SCR + gc], sm[SHR + gc]);
                        rv1 = fmaf(rv1, sm[SCR + gc + 1], sm[SHR + gc + 1]);
                    }
                    v0 += rv0;
                    v1 += rv1;
                }
                if (rok) *(float2*)(C + (size_t)r * ldc + gc) = make_float2(v0, v1);
                if (BN && rok) {
                    s0[ni] += v0; q0[ni] += v0 * v0;
                    s1[ni] += v1; q1[ni] += v1 * v1;
                }
                if (ELER) {
                    int h = ((bn + n0) >> 3) + ni;
                    float p = fmaf(v0, sm[ALO + h * 8 + qk * 2], v1 * sm[ALO + h * 8 + qk * 2 + 1]);
                    float q = fmaf(v0, sm[ARO + h * 8 + qk * 2], v1 * sm[ARO + h * 8 + qk * 2 + 1]);
                    p += __shfl_xor_sync(0xffffffffu, p, 1);
                    p += __shfl_xor_sync(0xffffffffu, p, 2);
                    q += __shfl_xor_sync(0xffffffffu, q, 1);
                    q += __shfl_xor_sync(0xffffffffu, q, 2);
                    if ((lane & 3) == 0 && rok) {
                        g_el[r * 16 + h] = p;
                        g_er[r * 16 + h] = q;
                    }
                }
            }
        }
    }

    if (BN) {
#pragma unroll
        for (int ni = 0; ni < 8; ni++) {
            s0[ni] += __shfl_xor_sync(0xffffffffu, s0[ni], 4);
            s0[ni] += __shfl_xor_sync(0xffffffffu, s0[ni], 8);
            s0[ni] += __shfl_xor_sync(0xffffffffu, s0[ni], 16);
            s1[ni] += __shfl_xor_sync(0xffffffffu, s1[ni], 4);
            s1[ni] += __shfl_xor_sync(0xffffffffu, s1[ni], 8);
            s1[ni] += __shfl_xor_sync(0xffffffffu, s1[ni], 16);
            q0[ni] += __shfl_xor_sync(0xffffffffu, q0[ni], 4);
            q0[ni] += __shfl_xor_sync(0xffffffffu, q0[ni], 8);
            q0[ni] += __shfl_xor_sync(0xffffffffu, q0[ni], 16);
            q1[ni] += __shfl_xor_sync(0xffffffffu, q1[ni], 4);
            q1[ni] += __shfl_xor_sync(0xffffffffu, q1[ni], 8);
            q1[ni] += __shfl_xor_sync(0xffffffffu, q1[ni], 16);
        }
        __syncthreads();
        if (lane < 4) {
            int mg = wid & 3;
#pragma unroll
            for (int ni = 0; ni < 8; ni++) {
                int c = n0 + ni * 8 + lane * 2;
                sm[mg * 128 + c] = s0[ni];
                sm[mg * 128 + c + 1] = s1[ni];
                sm[512 + mg * 128 + c] = q0[ni];
                sm[512 + mg * 128 + c + 1] = q1[ni];
            }
        }
        __syncthreads();
        {
            int c = tid & 127, st = tid >> 7;
            float v = sm[st * 512 + c] + sm[st * 512 + 128 + c] +
                      sm[st * 512 + 256 + c] + sm[st * 512 + 384 + c];
            atomicAdd(bnslot + st * 128 + c, v);
        }
    }
}

// ---------------- GAT aggregate (warp per node) + residual affine + fused BN1 stats ----------------
__global__ void k_gat(const float* __restrict__ z, const int* __restrict__ src,
                      const float* __restrict__ hres, int ldh,
                      const float* __restrict__ bias, float* __restrict__ y,
                      float* __restrict__ bnslot,
                      const float* __restrict__ slotPrev,
                      const float* __restrict__ gPrev, const float* __restrict__ bPrev) {
    __shared__ float sbn[2][8][128];
    int gw = (blockIdx.x * blockDim.x + threadIdx.x) >> 5;
    int lane = threadIdx.x & 31;
    int wid = threadIdx.x >> 5;
    float4 o = make_float4(0.f, 0.f, 0.f, 0.f);
    if (gw < Nn) {
        int head = lane >> 1;
        int beg = g_rowptr[gw], end = g_rowptr[gw + 1];
        float er_h = g_er[gw * 16 + head];

        float m = -1e30f;
        for (int i = beg; i < end; i++) {
            int s = src[g_eid[i]];
            float v = g_el[s * 16 + head] + er_h;
            v = v > 0.f ? v : SLOPE * v;
            m = fmaxf(m, v);
        }
        float den = 0.f;
        float4 acc = make_float4(0.f, 0.f, 0.f, 0.f);
        const float4* z4 = (const float4*)z;
        for (int i = beg; i < end; i++) {
            int s = src[g_eid[i]];
            float v = g_el[s * 16 + head] + er_h;
            v = v > 0.f ? v : SLOPE * v;
            float w = expf(v - m);
            den += w;
            float4 zv = z4[(size_t)s * 32 + lane];
            acc.x += w * zv.x; acc.y += w * zv.y; acc.z += w * zv.z; acc.w += w * zv.w;
        }
        float dinv = den > 0.f ? 1.f / den : 1.f;
        float4 b4 = ((const float4*)bias)[lane];
        float4 h4 = *(const float4*)(hres + (size_t)gw * ldh + lane * 4);
        if (slotPrev != nullptr) {
            const float invN = 1.f / (float)Nn;
            int c = lane * 4;
#pragma unroll
            for (int j = 0; j < 4; j++) {
                float mu = slotPrev[c + j] * invN;
                float var = slotPrev[128 + c + j] * invN - mu * mu;
                float sc = gPrev[c + j] * rsqrtf(var + EPSBN);
                float sh = bPrev[c + j] - mu * sc;
                float* hp = (&h4.x) + j;
                *hp = fmaf(*hp, sc, sh);
            }
        }
        o.x = acc.x * dinv + b4.x + h4.x;
        o.y = acc.y * dinv + b4.y + h4.y;
        o.z = acc.z * dinv + b4.z + h4.z;
        o.w = acc.w * dinv + b4.w + h4.w;
        ((float4*)y)[(size_t)gw * 32 + lane] = o;
    }
    ((float4*)sbn[0][wid])[lane] = o;
    ((float4*)sbn[1][wid])[lane] = make_float4(o.x * o.x, o.y * o.y, o.z * o.z, o.w * o.w);
    __syncthreads();
    int c = threadIdx.x & 127, st = threadIdx.x >> 7;
    float v = 0.f;
#pragma unroll
    for (int w = 0; w < 8; w++) v += sbn[st][w][c];
    atomicAdd(bnslot + st * 128 + c, v);
}

// ---------------- decoder final dot ----------------
__global__ void k_dec_out(const float* __restrict__ t, const float* __restrict__ W2,
                          const float* __restrict__ b2, float* __restrict__ out) {
    int warp = (blockIdx.x * blockDim.x + threadIdx.x) >> 5;
    if (warp >= Nn) return;
    int lane = threadIdx.x & 31;
    float4 tv = ((const float4*)t)[(size_t)warp * 32 + lane];
    float4 wv = ((const float4*)W2)[lane];
    float s = tv.x * wv.x + tv.y * wv.y + tv.z * wv.z + tv.w * wv.w;
#pragma unroll
    for (int o = 16; o; o >>= 1) s += __shfl_down_sync(0xffffffffu, s, o);
    if (lane == 0) out[warp] = s + b2[0];
}

// ---------------- launch ----------------
extern "C" void kernel_launch(void* const* d_in, const int* in_sizes, int n_in,
                              void* d_out, int out_size) {
    const float* x      = (const float*)d_in[0];
    const int*   src    = (const int*)d_in[1];
    const int*   dst    = (const int*)d_in[2];
    const float* emb_W1 = (const float*)d_in[3];
    const float* emb_b1 = (const float*)d_in[4];
    const float* emb_W2 = (const float*)d_in[5];
    const float* emb_b2 = (const float*)d_in[6];
    const float* emb_Ws = (const float*)d_in[7];
    const float* emb_bs = (const float*)d_in[8];
    const float* gat_W  = (const float*)d_in[9];
    const float* gat_al = (const float*)d_in[10];
    const float* gat_ar = (const float*)d_in[11];
    const float* gat_b  = (const float*)d_in[12];
    const float* bn1_g  = (const float*)d_in[13];
    const float* bn1_b  = (const float*)d_in[14];
    const float* ff_W1  = (const float*)d_in[15];
    const float* ff_b1  = (const float*)d_in[16];
    const float* ff_W2  = (const float*)d_in[17];
    const float* ff_b2  = (const float*)d_in[18];
    const float* bn2_g  = (const float*)d_in[19];
    const float* bn2_b  = (const float*)d_in[20];
    const float* dec_W1 = (const float*)d_in[21];
    const float* dec_b1 = (const float*)d_in[22];
    const float* dec_W2 = (const float*)d_in[23];
    const float* dec_b2 = (const float*)d_in[24];

    void* p;
    float *HC, *zb, *tb, *yb, *bns, *W;
    int* degp;
    cudaGetSymbolAddress(&p, g_HC);    HC = (float*)p;
    cudaGetSymbolAddress(&p, g_z);     zb = (float*)p;
    cudaGetSymbolAddress(&p, g_t);     tb = (float*)p;
    cudaGetSymbolAddress(&p, g_y);     yb = (float*)p;
    cudaGetSymbolAddress(&p, g_bnsum); bns = (float*)p;
    cudaGetSymbolAddress(&p, g_deg);   degp = (int*)p;
    cudaGetSymbolAddress(&p, g_W);     W = (float*)p;

    float* Wg = W;            // [4][128,128]
    float* Wf1 = W + 65536;   // [4][128,256]
    float* Wf2 = W + 196608;  // [4][256,128]
    float* Wd = W + 327680;   // [640,128]
    float* We2 = W + 409600;  // [128,128]

    const int SMEM = 20736 * 4;  // 82944 B
    static bool attrDone = false;
    if (!attrDone) {
        cudaFuncSetAttribute(k_tgemm<0, 0, 1, 0, 0, 0, 0>, cudaFuncAttributeMaxDynamicSharedMemorySize, SMEM);
        cudaFuncSetAttribute(k_tgemm<0, 0, 0, 0, 1, 0, 0>, cudaFuncAttributeMaxDynamicSharedMemorySize, SMEM);
        cudaFuncSetAttribute(k_tgemm<0, 0, 0, 0, 1, 1, 0>, cudaFuncAttributeMaxDynamicSharedMemorySize, SMEM);
        cudaFuncSetAttribute(k_tgemm<1, 1, 0, 0, 0, 1, 0>, cudaFuncAttributeMaxDynamicSharedMemorySize, SMEM);
        cudaFuncSetAttribute(k_tgemm<0, 1, 1, 1, 0, 0, 1>, cudaFuncAttributeMaxDynamicSharedMemorySize, SMEM);
        cudaFuncSetAttribute(k_tgemm<1, 1, 0, 0, 0, 2, 0>, cudaFuncAttributeMaxDynamicSharedMemorySize, SMEM);
        attrDone = true;
    }

    cudaMemsetAsync(bns, 0, 8 * 256 * sizeof(float));
    cudaMemsetAsync(degp, 0, Nn * sizeof(int));

    k_cvt_all<<<(425984 + 255) / 256, 256>>>(gat_W, ff_W1, ff_W2, dec_W1, emb_W2);
    k_embed1<<<(Nn * 128 + 255) / 256, 256>>>(x, emb_W1, emb_b1, emb_b2, emb_Ws, emb_bs);
    k_count<<<(Ee + 255) / 256, 256>>>(dst);

    const int gx = (Nn + 127) / 128;  // 782
    dim3 grid1(gx, 1), grid2(gx, 2);
    const int warpBlocks = (Nn * 32 + 255) / 256;

    // embed stage 2 GEMM (6th launch -> ncu target)
    k_tgemm<0, 0, 1, 0, 0, 0, 0><<<grid1, 256, SMEM>>>(
        tb, 128, We2, nullptr, yb, 128, HC, 640, Nn, 128, 128, nullptr,
        nullptr, nullptr, nullptr, nullptr, nullptr, nullptr, nullptr, nullptr);

    const int nb = (Nn + 1023) / 1024;
    k_scan1<<<nb, 1024>>>();
    k_scan2<<<1, 128>>>(nb);
    k_finalize<<<(Nn + 255) / 256, 256>>>();
    k_fill<<<(Ee + 255) / 256, 256>>>(dst);

    for (int l = 0; l < 4; l++) {
        const float* h = HC + l * 128;
        float* slot1 = bns + (size_t)(2 * l) * 256;
        float* slot2 = bns + (size_t)(2 * l + 1) * 256;
        const float* slotP = (l > 0) ? (bns + (size_t)(2 * (l - 1) + 1) * 256) : nullptr;
        const float* gP = (l > 0) ? (bn2_g + (l - 1) * 128) : nullptr;
        const float* bP = (l > 0) ? (bn2_b + (l - 1) * 128) : nullptr;

        // z = BN2prev(h) @ gat_W[l]  (+ fused el/er)
        if (l == 0) {
            k_tgemm<0, 0, 0, 0, 1, 0, 0><<<grid1, 256, SMEM>>>(
                h, 640, Wg, nullptr, nullptr, 0, zb, 128, Nn, 128, 128, nullptr,
                nullptr, nullptr, nullptr, nullptr, nullptr, nullptr,
                gat_al, gat_ar);
        } else {
            k_tgemm<0, 0, 0, 0, 1, 1, 0><<<grid1, 256, SMEM>>>(
                h, 640, Wg + (size_t)l * 16384, nullptr, nullptr, 0, zb, 128, Nn, 128, 128, nullptr,
                slotP, gP, bP, nullptr, nullptr, nullptr,
                gat_al + l * 128, gat_ar + l * 128);
        }
        k_gat<<<warpBlocks, 256>>>(zb, src, h, 640, gat_b + l * 128, yb, slot1, slotP, gP, bP);
        // ff1: relu(BN1(yb) @ W1 + b1)
        k_tgemm<1, 1, 0, 0, 0, 1, 0><<<grid2, 256, SMEM>>>(
            yb, 128, Wf1 + (size_t)l * 32768, ff_b1 + l * 256, nullptr, 0, tb, 256,
            Nn, 128, 256, nullptr,
            slot1, bn1_g + l * 128, bn1_b + l * 128, nullptr, nullptr, nullptr, nullptr, nullptr);
        // ff2: t @ W2 + b2 + BN1(yb)  -> HC block l+1 (raw), BN2 stats fused
        k_tgemm<0, 1, 1, 1, 0, 0, 1><<<grid1, 256, SMEM>>>(
            tb, 256, Wf2 + (size_t)l * 32768, ff_b2 + l * 128, yb, 128,
            HC + (size_t)(l + 1) * 128, 640, Nn, 256, 128, slot2,
            nullptr, nullptr, nullptr, slot1, bn1_g + l * 128, bn1_b + l * 128, nullptr, nullptr);
    }

    // decoder: relu(affine_concat(HC) @ Wd + b1)
    k_tgemm<1, 1, 0, 0, 0, 2, 0><<<grid1, 256, SMEM>>>(
        HC, 640, Wd, dec_b1, nullptr, 0, tb, 128, Nn, 640, 128, nullptr,
        nullptr, bn2_g, bn2_b, nullptr, nullptr, nullptr, nullptr, nullptr);
    k_dec_out<<<warpBlocks, 256>>>(tb, dec_W2, dec_b2, (float*)d_out);
}

// round 7
// speedup vs baseline: 2.4756x; 1.0052x over previous
#include <cuda_runtime.h>
#include <cstdint>

#define Nn 100000
#define Ee 600000
#define EPSBN 1e-5f
#define SLOPE 0.2f

// ---------------- scratch ----------------
__device__ float g_HC[(size_t)Nn * 640];
__device__ float g_z[(size_t)Nn * 128];
__device__ float g_t[(size_t)Nn * 256];
__device__ float g_y[(size_t)Nn * 128];
__device__ float g_el[(size_t)Nn * 16];
__device__ float g_er[(size_t)Nn * 16];
__device__ float g_bnsum[8 * 256];
__device__ int   g_deg[Nn];
__device__ int   g_scan[Nn];
__device__ int   g_bsum[128];
__device__ int   g_rowptr[Nn + 1];
__device__ int   g_cursor[Nn];
__device__ int   g_srcs[Ee];
__device__ float g_W[425984];

__device__ __forceinline__ float to_tf32(float x) {
    float r;
    asm("cvt.rna.tf32.f32 %0, %1;" : "=f"(r) : "f"(x));
    return r;
}
__device__ __forceinline__ uint32_t smem_to_u32(const void* p) {
    uint32_t a;
    asm("{ .reg .u64 t; cvta.to.shared.u64 t, %1; cvt.u32.u64 %0, t; }" : "=r"(a) : "l"(p));
    return a;
}
__device__ __forceinline__ void cp16(uint32_t dst, const void* src, bool ok) {
    int sz = ok ? 16 : 0;
    asm volatile("cp.async.cg.shared.global [%0], [%1], 16, %2;"
                 :: "r"(dst), "l"(src), "r"(sz) : "memory");
}
#define CP_COMMIT() asm volatile("cp.async.commit_group;" ::: "memory")
#define CP_WAIT2() asm volatile("cp.async.wait_group 2;" ::: "memory")

#define MMA_TF32(d, av, bv)                                               \
    asm volatile(                                                         \
        "mma.sync.aligned.m16n8k8.row.col.f32.tf32.tf32.f32 "             \
        "{%0,%1,%2,%3},{%4,%5,%6,%7},{%8,%9},{%0,%1,%2,%3};"              \
        : "+f"((d)[0]), "+f"((d)[1]), "+f"((d)[2]), "+f"((d)[3])          \
        : "r"((av)[0]), "r"((av)[1]), "r"((av)[2]), "r"((av)[3]),         \
          "r"((bv)[0]), "r"((bv)[1]))

// ---------------- CSR build ----------------
__global__ void k_count(const int* __restrict__ dst) {
    int e = blockIdx.x * blockDim.x + threadIdx.x;
    if (e < Ee) atomicAdd(&g_deg[dst[e]], 1);
}
__global__ void k_scan1() {
    __shared__ int s[1024];
    int i = blockIdx.x * 1024 + threadIdx.x;
    int v = (i < Nn) ? g_deg[i] : 0;
    s[threadIdx.x] = v;
    __syncthreads();
    for (int off = 1; off < 1024; off <<= 1) {
        int t = (threadIdx.x >= off) ? s[threadIdx.x - off] : 0;
        __syncthreads();
        s[threadIdx.x] += t;
        __syncthreads();
    }
    if (i < Nn) g_scan[i] = s[threadIdx.x];
    if (threadIdx.x == 1023) g_bsum[blockIdx.x] = s[1023];
}
__global__ void k_scan2(int nb) {
    __shared__ int s[128];
    int v = (threadIdx.x < nb) ? g_bsum[threadIdx.x] : 0;
    s[threadIdx.x] = v;
    __syncthreads();
    for (int off = 1; off < 128; off <<= 1) {
        int t = (threadIdx.x >= off) ? s[threadIdx.x - off] : 0;
        __syncthreads();
        s[threadIdx.x] += t;
        __syncthreads();
    }
    g_bsum[threadIdx.x] = (threadIdx.x == 0) ? 0 : s[threadIdx.x - 1];
}
__global__ void k_finalize() {
    int i = blockIdx.x * blockDim.x + threadIdx.x;
    if (i >= Nn) return;
    int incl = g_scan[i] + g_bsum[i >> 10];
    g_rowptr[i + 1] = incl;
    g_cursor[i] = incl - g_deg[i];
    if (i == 0) g_rowptr[0] = 0;
}
__global__ void k_fill(const int* __restrict__ dst, const int* __restrict__ src) {
    int e = blockIdx.x * blockDim.x + threadIdx.x;
    if (e < Ee) {
        int d = dst[e];
        int p = atomicAdd(&g_cursor[d], 1);
        g_srcs[p] = src[e];
    }
}

// ---------------- all-weight cvt ----------------
__global__ void k_cvt_all(const float* __restrict__ gat_W, const float* __restrict__ ff_W1,
                          const float* __restrict__ ff_W2, const float* __restrict__ dec_W1,
                          const float* __restrict__ emb_W2) {
    int i = blockIdx.x * blockDim.x + threadIdx.x;
    if (i >= 425984) return;
    float v;
    if (i < 65536) v = gat_W[i];
    else if (i < 196608) v = ff_W1[i - 65536];
    else if (i < 327680) v = ff_W2[i - 196608];
    else if (i < 409600) v = dec_W1[i - 327680];
    else v = emb_W2[i - 409600];
    g_W[i] = to_tf32(v);
}

// ---------------- embed stage 1 ----------------
__global__ void k_embed1(const float* __restrict__ x,
                         const float* __restrict__ W1, const float* __restrict__ b1,
                         const float* __restrict__ b2,
                         const float* __restrict__ Ws, const float* __restrict__ bs) {
    int idx = blockIdx.x * blockDim.x + threadIdx.x;
    if (idx >= Nn * 128) return;
    int n = idx >> 7, c = idx & 127;
    float x0 = x[n * 2], x1 = x[n * 2 + 1];
    float tv = fmaf(x0, W1[c], fmaf(x1, W1[128 + c], b1[c]));
    g_t[idx] = tv > 0.f ? tv : 0.f;
    g_y[idx] = fmaf(x0, Ws[c], fmaf(x1, Ws[128 + c], bs[c] + b2[c]));
}

// ---------------- fused tf32 tensor GEMM (512 thr, 16 warps of 32x32) ----------------
template <int RELU, int BIAS, int RES, int BN, int ELER, int AAFF, int RAFF, int DEC>
__global__ void __launch_bounds__(512, 2) k_tgemm(
    const float* __restrict__ A, int lda,
    const float* __restrict__ B,
    const float* __restrict__ bias,
    const float* __restrict__ Res, int ldres,
    float* __restrict__ C, int ldc,
    int Nrows, int Mred, int Kcols, float* bnslot,
    const float* affA, const float* affAg, const float* affAb,
    const float* affR, const float* affRg, const float* affRb,
    const float* al, const float* ar) {
    constexpr int S = 4;
    constexpr int ASTG = 128 * 20;
    constexpr int BSTG = 16 * 136;
    constexpr int STGF = S * ASTG + S * BSTG;
    constexpr int SCA = STGF, SHA = SCA + 640, SCR = SHA + 640, SHR = SCR + 128;
    constexpr int ALO = SHR + 128, ARO = ALO + 128;
    extern __shared__ float sm[];
    float* AsF = sm;
    float* BsF = sm + S * ASTG;

    const int tid = threadIdx.x;
    const int lane = tid & 31;
    const int wid = tid >> 5;  // 0..15
    const int bm = blockIdx.x * 128;
    const int bn = blockIdx.y * 128;

    const int m0 = (wid & 3) * 32;
    const int n0 = (wid >> 2) * 32;
    const int qrow = lane >> 2;
    const int qk = lane & 3;

    // loaders: one 16B cp per thread per matrix per stage
    const int arow = tid >> 2;        // 0..127
    const int aseg = (tid & 3) * 4;   // 0,4,8,12
    const int brow = tid >> 5;        // 0..15
    const int bcol = (tid & 31) * 4;  // 0..124

    const int gr = bm + arow;
    const bool aok = gr < Nrows;
    const float* Asrc = A + (size_t)gr * lda + aseg;
    const float* Bsrc = B + (size_t)brow * Kcols + bn + bcol;
    const uint32_t adst = smem_to_u32(AsF) + (uint32_t)(arow * 20 + aseg) * 4u;
    const uint32_t bdst = smem_to_u32(BsF) + (uint32_t)(brow * 136 + bcol) * 4u;

    const int nIter = Mred >> 4;

#pragma unroll
    for (int s = 0; s < S - 1; s++) {
        if (s < nIter) {
            int kt = s << 4;
            cp16(adst + (uint32_t)(s * ASTG) * 4u, Asrc + kt, aok);
            cp16(bdst + (uint32_t)(s * BSTG) * 4u, Bsrc + (size_t)kt * Kcols, true);
        }
        CP_COMMIT();
    }

    const float invN = 1.f / (float)Nn;
    if (AAFF) {
        for (int k = tid; k < Mred; k += 512) {
            float scv = 1.f, shv = 0.f;
            const float *slot = nullptr, *gg = nullptr, *bb = nullptr;
            int c = k;
            if (AAFF == 1) { slot = affA; gg = affAg; bb = affAb; }
            else {
                int blk = k >> 7;
                c = k & 127;
                if (blk > 0) {
                    slot = g_bnsum + (size_t)(2 * (blk - 1) + 1) * 256;
                    gg = affAg + (blk - 1) * 128;
                    bb = affAb + (blk - 1) * 128;
                }
            }
            if (slot) {
                float mu = slot[c] * invN;
                float var = slot[c + 128] * invN - mu * mu;
                float rs = rsqrtf(var + EPSBN);
                scv = gg[c] * rs;
                shv = bb[c] - mu * scv;
            }
            sm[SCA + k] = scv;
            sm[SHA + k] = shv;
        }
    }
    if (RAFF) {
        if (tid < 128) {
            float mu = affR[tid] * invN;
            float var = affR[tid + 128] * invN - mu * mu;
            float rs = rsqrtf(var + EPSBN);
            float scv = affRg[tid] * rs;
            sm[SCR + tid] = scv;
            sm[SHR + tid] = affRb[tid] - mu * scv;
        }
    }
    if (ELER) {
        if (tid < 128) sm[ALO + tid] = al[tid];
        else if (tid < 256) sm[ARO + tid - 128] = ar[tid - 128];
    }
    if (DEC) {
        if (tid < 128) sm[ALO + tid] = al[tid];  // dec_W2
    }

    float acc[2][4][4];
#pragma unroll
    for (int mi = 0; mi < 2; mi++)
#pragma unroll
        for (int ni = 0; ni < 4; ni++)
#pragma unroll
            for (int j = 0; j < 4; j++) acc[mi][ni][j] = 0.f;

    for (int it = 0; it < nIter; it++) {
        CP_WAIT2();
        __syncthreads();

        const int stg = it & (S - 1);
        const float* as = AsF + stg * ASTG;
        const float* bs = BsF + stg * BSTG;
#pragma unroll
        for (int ks = 0; ks < 2; ks++) {
            const int kbase = ks * 8;
            float sc0 = 1.f, sc1 = 1.f, sh0 = 0.f, sh1 = 0.f;
            if (AAFF) {
                int kg = (it << 4) + kbase + qk;
                sc0 = sm[SCA + kg]; sh0 = sm[SHA + kg];
                sc1 = sm[SCA + kg + 4]; sh1 = sm[SHA + kg + 4];
            }
            uint32_t a[2][4];
#pragma unroll
            for (int mi = 0; mi < 2; mi++) {
                const float* ap = as + (m0 + mi * 16 + qrow) * 20 + kbase + qk;
                if (AAFF) {
                    a[mi][0] = __float_as_uint(to_tf32(fmaf(ap[0], sc0, sh0)));
                    a[mi][1] = __float_as_uint(to_tf32(fmaf(ap[8 * 20], sc0, sh0)));
                    a[mi][2] = __float_as_uint(to_tf32(fmaf(ap[4], sc1, sh1)));
                    a[mi][3] = __float_as_uint(to_tf32(fmaf(ap[8 * 20 + 4], sc1, sh1)));
                } else {
                    a[mi][0] = __float_as_uint(to_tf32(ap[0]));
                    a[mi][1] = __float_as_uint(to_tf32(ap[8 * 20]));
                    a[mi][2] = __float_as_uint(to_tf32(ap[4]));
                    a[mi][3] = __float_as_uint(to_tf32(ap[8 * 20 + 4]));
                }
            }
            uint32_t b[4][2];
#pragma unroll
            for (int ni = 0; ni < 4; ni++) {
                const float* bp = bs + (kbase + qk) * 136 + n0 + ni * 8 + qrow;
                b[ni][0] = __float_as_uint(bp[0]);
                b[ni][1] = __float_as_uint(bp[4 * 136]);
            }
#pragma unroll
            for (int mi = 0; mi < 2; mi++)
#pragma unroll
                for (int ni = 0; ni < 4; ni++) MMA_TF32(acc[mi][ni], a[mi], b[ni]);
        }

        const int nx = it + S - 1;
        if (nx < nIter) {
            const int s = nx & (S - 1);
            const int kt = nx << 4;
            cp16(adst + (uint32_t)(s * ASTG) * 4u, Asrc + kt, aok);
            cp16(bdst + (uint32_t)(s * BSTG) * 4u, Bsrc + (size_t)kt * Kcols, true);
        }
        CP_COMMIT();
    }

    // epilogue
    float s0[4], s1[4], q0[4], q1[4];
    if (BN) {
#pragma unroll
        for (int ni = 0; ni < 4; ni++) { s0[ni] = 0.f; s1[ni] = 0.f; q0[ni] = 0.f; q1[ni] = 0.f; }
    }
#pragma unroll
    for (int mi = 0; mi < 2; mi++) {
#pragma unroll
        for (int half = 0; half < 2; half++) {
            int r = bm + m0 + mi * 16 + qrow + half * 8;
            bool rok = r < Nrows;
            float pd = 0.f;
#pragma unroll
            for (int ni = 0; ni < 4; ni++) {
                int gcl = n0 + ni * 8 + qk * 2;
                int gc = bn + gcl;
                float v0 = acc[mi][ni][half * 2 + 0];
                float v1 = acc[mi][ni][half * 2 + 1];
                if (BIAS) {
                    v0 += bias[gc];
                    v1 += bias[gc + 1];
                }
                if (RELU) {
                    v0 = fmaxf(v0, 0.f);
                    v1 = fmaxf(v1, 0.f);
                }
                if (RES && rok) {
                    const float* rp = Res + (size_t)r * ldres + gc;
                    float rv0 = rp[0], rv1 = rp[1];
                    if (RAFF) {
                        rv0 = fmaf(rv0, sm[SCR + gc], sm[SHR + gc]);
                        rv1 = fmaf(rv1, sm[SCR + gc + 1], sm[SHR + gc + 1]);
                    }
                    v0 += rv0;
                    v1 += rv1;
                }
                if (!DEC && rok) *(float2*)(C + (size_t)r * ldc + gc) = make_float2(v0, v1);
                if (BN && rok) {
                    s0[ni] += v0; q0[ni] += v0 * v0;
                    s1[ni] += v1; q1[ni] += v1 * v1;
                }
                if (DEC) pd = fmaf(v0, sm[ALO + gcl], fmaf(v1, sm[ALO + gcl + 1], pd));
                if (ELER) {
                    int h = (n0 >> 3) + ni;
                    float p = fmaf(v0, sm[ALO + h * 8 + qk * 2], v1 * sm[ALO + h * 8 + qk * 2 + 1]);
                    float q = fmaf(v0, sm[ARO + h * 8 + qk * 2], v1 * sm[ARO + h * 8 + qk * 2 + 1]);
                    p += __shfl_xor_sync(0xffffffffu, p, 1);
                    p += __shfl_xor_sync(0xffffffffu, p, 2);
                    q += __shfl_xor_sync(0xffffffffu, q, 1);
                    q += __shfl_xor_sync(0xffffffffu, q, 2);
                    if ((lane & 3) == 0 && rok) {
                        g_el[r * 16 + h] = p;
                        g_er[r * 16 + h] = q;
                    }
                }
            }
            if (DEC) {
                pd += __shfl_xor_sync(0xffffffffu, pd, 1);
                pd += __shfl_xor_sync(0xffffffffu, pd, 2);
                if ((lane & 3) == 0 && rok)
                    atomicAdd(C + r, pd + 0.25f * ar[0]);
            }
        }
    }

    if (BN) {
#pragma unroll
        for (int ni = 0; ni < 4; ni++) {
            s0[ni] += __shfl_xor_sync(0xffffffffu, s0[ni], 4);
            s0[ni] += __shfl_xor_sync(0xffffffffu, s0[ni], 8);
            s0[ni] += __shfl_xor_sync(0xffffffffu, s0[ni], 16);
            s1[ni] += __shfl_xor_sync(0xffffffffu, s1[ni], 4);
            s1[ni] += __shfl_xor_sync(0xffffffffu, s1[ni], 8);
            s1[ni] += __shfl_xor_sync(0xffffffffu, s1[ni], 16);
            q0[ni] += __shfl_xor_sync(0xffffffffu, q0[ni], 4);
            q0[ni] += __shfl_xor_sync(0xffffffffu, q0[ni], 8);
            q0[ni] += __shfl_xor_sync(0xffffffffu, q0[ni], 16);
            q1[ni] += __shfl_xor_sync(0xffffffffu, q1[ni], 4);
            q1[ni] += __shfl_xor_sync(0xffffffffu, q1[ni], 8);
            q1[ni] += __shfl_xor_sync(0xffffffffu, q1[ni], 16);
        }
        __syncthreads();
        if (lane < 4) {
            int mg = wid & 3;
#pragma unroll
            for (int ni = 0; ni < 4; ni++) {
                int c = n0 + ni * 8 + lane * 2;
                sm[mg * 128 + c] = s0[ni];
                sm[mg * 128 + c + 1] = s1[ni];
                sm[512 + mg * 128 + c] = q0[ni];
                sm[512 + mg * 128 + c + 1] = q1[ni];
            }
        }
        __syncthreads();
        if (tid < 256) {
            int c = tid & 127, st = tid >> 7;
            float v = sm[st * 512 + c] + sm[st * 512 + 128 + c] +
                      sm[st * 512 + 256 + c] + sm[st * 512 + 384 + c];
            atomicAdd(bnslot + st * 128 + c, v);
        }
    }
}

// ---------------- GAT aggregate (warp per node) + residual affine + fused BN1 stats ----------------
__global__ void k_gat(const float* __restrict__ z,
                      const float* __restrict__ hres, int ldh,
                      const float* __restrict__ bias, float* __restrict__ y,
                      float* __restrict__ bnslot,
                      const float* __restrict__ slotPrev,
                      const float* __restrict__ gPrev, const float* __restrict__ bPrev) {
    __shared__ float sbn[2][8][128];
    int gw = (blockIdx.x * blockDim.x + threadIdx.x) >> 5;
    int lane = threadIdx.x & 31;
    int wid = threadIdx.x >> 5;
    float4 o = make_float4(0.f, 0.f, 0.f, 0.f);
    if (gw < Nn) {
        int head = lane >> 1;
        int beg = g_rowptr[gw], end = g_rowptr[gw + 1];
        float er_h = g_er[gw * 16 + head];

        float m = -1e30f;
        for (int i = beg; i < end; i++) {
            int s = g_srcs[i];
            float v = g_el[s * 16 + head] + er_h;
            v = v > 0.f ? v : SLOPE * v;
            m = fmaxf(m, v);
        }
        float den = 0.f;
        float4 acc = make_float4(0.f, 0.f, 0.f, 0.f);
        const float4* z4 = (const float4*)z;
        for (int i = beg; i < end; i++) {
            int s = g_srcs[i];
            float v = g_el[s * 16 + head] + er_h;
            v = v > 0.f ? v : SLOPE * v;
            float w = expf(v - m);
            den += w;
            float4 zv = z4[(size_t)s * 32 + lane];
            acc.x += w * zv.x; acc.y += w * zv.y; acc.z += w * zv.z; acc.w += w * zv.w;
        }
        float dinv = den > 0.f ? 1.f / den : 1.f;
        float4 b4 = ((const float4*)bias)[lane];
        float4 h4 = *(const float4*)(hres + (size_t)gw * ldh + lane * 4);
        if (slotPrev != nullptr) {
            const float invN = 1.f / (float)Nn;
            int c = lane * 4;
#pragma unroll
            for (int j = 0; j < 4; j++) {
                float mu = slotPrev[c + j] * invN;
                float var = slotPrev[128 + c + j] * invN - mu * mu;
                float sc = gPrev[c + j] * rsqrtf(var + EPSBN);
                float sh = bPrev[c + j] - mu * sc;
                float* hp = (&h4.x) + j;
                *hp = fmaf(*hp, sc, sh);
            }
        }
        o.x = acc.x * dinv + b4.x + h4.x;
        o.y = acc.y * dinv + b4.y + h4.y;
        o.z = acc.z * dinv + b4.z + h4.z;
        o.w = acc.w * dinv + b4.w + h4.w;
        ((float4*)y)[(size_t)gw * 32 + lane] = o;
    }
    ((float4*)sbn[0][wid])[lane] = o;
    ((float4*)sbn[1][wid])[lane] = make_float4(o.x * o.x, o.y * o.y, o.z * o.z, o.w * o.w);
    __syncthreads();
    int c = threadIdx.x & 127, st = threadIdx.x >> 7;
    float v = 0.f;
#pragma unroll
    for (int w = 0; w < 8; w++) v += sbn[st][w][c];
    atomicAdd(bnslot + st * 128 + c, v);
}

// ---------------- launch ----------------
extern "C" void kernel_launch(void* const* d_in, const int* in_sizes, int n_in,
                              void* d_out, int out_size) {
    const float* x      = (const float*)d_in[0];
    const int*   src    = (const int*)d_in[1];
    const int*   dst    = (const int*)d_in[2];
    const float* emb_W1 = (const float*)d_in[3];
    const float* emb_b1 = (const float*)d_in[4];
    const float* emb_W2 = (const float*)d_in[5];
    const float* emb_b2 = (const float*)d_in[6];
    const float* emb_Ws = (const float*)d_in[7];
    const float* emb_bs = (const float*)d_in[8];
    const float* gat_W  = (const float*)d_in[9];
    const float* gat_al = (const float*)d_in[10];
    const float* gat_ar = (const float*)d_in[11];
    const float* gat_b  = (const float*)d_in[12];
    const float* bn1_g  = (const float*)d_in[13];
    const float* bn1_b  = (const float*)d_in[14];
    const float* ff_W1  = (const float*)d_in[15];
    const float* ff_b1  = (const float*)d_in[16];
    const float* ff_W2  = (const float*)d_in[17];
    const float* ff_b2  = (const float*)d_in[18];
    const float* bn2_g  = (const float*)d_in[19];
    const float* bn2_b  = (const float*)d_in[20];
    const float* dec_W1 = (const float*)d_in[21];
    const float* dec_b1 = (const float*)d_in[22];
    const float* dec_W2 = (const float*)d_in[23];
    const float* dec_b2 = (const float*)d_in[24];

    void* p;
    float *HC, *zb, *tb, *yb, *bns, *W;
    int* degp;
    cudaGetSymbolAddress(&p, g_HC);    HC = (float*)p;
    cudaGetSymbolAddress(&p, g_z);     zb = (float*)p;
    cudaGetSymbolAddress(&p, g_t);     tb = (float*)p;
    cudaGetSymbolAddress(&p, g_y);     yb = (float*)p;
    cudaGetSymbolAddress(&p, g_bnsum); bns = (float*)p;
    cudaGetSymbolAddress(&p, g_deg);   degp = (int*)p;
    cudaGetSymbolAddress(&p, g_W);     W = (float*)p;

    float* Wg = W;
    float* Wf1 = W + 65536;
    float* Wf2 = W + 196608;
    float* Wd = W + 327680;
    float* We2 = W + 409600;

    const int SMEM = 20736 * 4;  // 82944 B
    static bool attrDone = false;
    if (!attrDone) {
        cudaFuncSetAttribute(k_tgemm<0, 0, 1, 0, 0, 0, 0, 0>, cudaFuncAttributeMaxDynamicSharedMemorySize, SMEM);
        cudaFuncSetAttribute(k_tgemm<0, 0, 0, 0, 1, 0, 0, 0>, cudaFuncAttributeMaxDynamicSharedMemorySize, SMEM);
        cudaFuncSetAttribute(k_tgemm<0, 0, 0, 0, 1, 1, 0, 0>, cudaFuncAttributeMaxDynamicSharedMemorySize, SMEM);
        cudaFuncSetAttribute(k_tgemm<1, 1, 0, 0, 0, 1, 0, 0>, cudaFuncAttributeMaxDynamicSharedMemorySize, SMEM);
        cudaFuncSetAttribute(k_tgemm<0, 1, 1, 1, 0, 0, 1, 0>, cudaFuncAttributeMaxDynamicSharedMemorySize, SMEM);
        cudaFuncSetAttribute(k_tgemm<1, 1, 0, 0, 0, 2, 0, 1>, cudaFuncAttributeMaxDynamicSharedMemorySize, SMEM);
        attrDone = true;
    }

    cudaMemsetAsync(bns, 0, 8 * 256 * sizeof(float));
    cudaMemsetAsync(degp, 0, Nn * sizeof(int));
    cudaMemsetAsync(d_out, 0, (size_t)out_size * sizeof(float));

    k_cvt_all<<<(425984 + 255) / 256, 256>>>(gat_W, ff_W1, ff_W2, dec_W1, emb_W2);
    k_embed1<<<(Nn * 128 + 255) / 256, 256>>>(x, emb_W1, emb_b1, emb_b2, emb_Ws, emb_bs);
    k_count<<<(Ee + 255) / 256, 256>>>(dst);

    const int gx = (Nn + 127) / 128;  // 782
    dim3 grid1(gx, 1), grid2(gx, 2);
    const int warpBlocks = (Nn * 32 + 255) / 256;

    // embed stage 2 GEMM
    k_tgemm<0, 0, 1, 0, 0, 0, 0, 0><<<grid1, 512, SMEM>>>(
        tb, 128, We2, nullptr, yb, 128, HC, 640, Nn, 128, 128, nullptr,
        nullptr, nullptr, nullptr, nullptr, nullptr, nullptr, nullptr, nullptr);

    const int nb = (Nn + 1023) / 1024;
    k_scan1<<<nb, 1024>>>();
    k_scan2<<<1, 128>>>(nb);
    k_finalize<<<(Nn + 255) / 256, 256>>>();
    k_fill<<<(Ee + 255) / 256, 256>>>(dst, src);

    for (int l = 0; l < 4; l++) {
        const float* h = HC + l * 128;
        float* slot1 = bns + (size_t)(2 * l) * 256;
        float* slot2 = bns + (size_t)(2 * l + 1) * 256;
        const float* slotP = (l > 0) ? (bns + (size_t)(2 * (l - 1) + 1) * 256) : nullptr;
        const float* gP = (l > 0) ? (bn2_g + (l - 1) * 128) : nullptr;
        const float* bP = (l > 0) ? (bn2_b + (l - 1) * 128) : nullptr;

        if (l == 0) {
            k_tgemm<0, 0, 0, 0, 1, 0, 0, 0><<<grid1, 512, SMEM>>>(
                h, 640, Wg, nullptr, nullptr, 0, zb, 128, Nn, 128, 128, nullptr,
                nullptr, nullptr, nullptr, nullptr, nullptr, nullptr,
                gat_al, gat_ar);
        } else {
            k_tgemm<0, 0, 0, 0, 1, 1, 0, 0><<<grid1, 512, SMEM>>>(
                h, 640, Wg + (size_t)l * 16384, nullptr, nullptr, 0, zb, 128, Nn, 128, 128, nullptr,
                slotP, gP, bP, nullptr, nullptr, nullptr,
                gat_al + l * 128, gat_ar + l * 128);
        }
        k_gat<<<warpBlocks, 256>>>(zb, h, 640, gat_b + l * 128, yb, slot1, slotP, gP, bP);
        k_tgemm<1, 1, 0, 0, 0, 1, 0, 0><<<grid2, 512, SMEM>>>(
            yb, 128, Wf1 + (size_t)l * 32768, ff_b1 + l * 256, nullptr, 0, tb, 256,
            Nn, 128, 256, nullptr,
            slot1, bn1_g + l * 128, bn1_b + l * 128, nullptr, nullptr, nullptr, nullptr, nullptr);
        k_tgemm<0, 1, 1, 1, 0, 0, 1, 0><<<grid1, 512, SMEM>>>(
            tb, 256, Wf2 + (size_t)l * 32768, ff_b2 + l * 128, yb, 128,
            HC + (size_t)(l + 1) * 128, 640, Nn, 256, 128, slot2,
            nullptr, nullptr, nullptr, slot1, bn1_g + l * 128, bn1_b + l * 128, nullptr, nullptr);
    }

    // decoder: relu(affine_concat(HC) @ Wd + b1) . W2 + b2  (fused dot, atomic partials)
    k_tgemm<1, 1, 0, 0, 0, 2, 0, 1><<<grid1, 512, SMEM>>>(
        HC, 640, Wd, dec_b1, nullptr, 0, (float*)d_out, 1, Nn, 640, 128, nullptr,
        nullptr, bn2_g, bn2_b, nullptr, nullptr, nullptr, dec_W2, dec_b2);
}

// round 10
// speedup vs baseline: 2.5893x; 1.0459x over previous
#include <cuda_runtime.h>
#include <cstdint>

#define Nn 100000
#define Ee 600000
#define EPSBN 1e-5f
#define SLOPE 0.2f

// ---------------- scratch ----------------
__device__ float g_HC[(size_t)Nn * 640];
__device__ float g_z[(size_t)Nn * 128];
__device__ float g_t[(size_t)Nn * 256];
__device__ float g_y[(size_t)Nn * 128];
__device__ float g_el[(size_t)Nn * 16];
__device__ float g_er[(size_t)Nn * 16];
__device__ float g_bnsum[8 * 256];
__device__ int   g_deg[Nn];
__device__ int   g_scan[Nn];
__device__ int   g_bsum[128];
__device__ int   g_rowptr[Nn + 1];
__device__ int   g_cursor[Nn];
__device__ int   g_srcs[Ee];
__device__ float g_W[425984];

__device__ __forceinline__ float to_tf32(float x) {
    float r;
    asm("cvt.rna.tf32.f32 %0, %1;" : "=f"(r) : "f"(x));
    return r;
}
__device__ __forceinline__ uint32_t smem_to_u32(const void* p) {
    uint32_t a;
    asm("{ .reg .u64 t; cvta.to.shared.u64 t, %1; cvt.u32.u64 %0, t; }" : "=r"(a) : "l"(p));
    return a;
}
__device__ __forceinline__ void cp16(uint32_t dst, const void* src, bool ok) {
    int sz = ok ? 16 : 0;
    asm volatile("cp.async.cg.shared.global [%0], [%1], 16, %2;"
                 :: "r"(dst), "l"(src), "r"(sz) : "memory");
}
#define CP_COMMIT() asm volatile("cp.async.commit_group;" ::: "memory")
#define CP_WAIT2() asm volatile("cp.async.wait_group 2;" ::: "memory")
#define CP_WAIT1() asm volatile("cp.async.wait_group 1;" ::: "memory")
#define CP_WAIT0() asm volatile("cp.async.wait_group 0;" ::: "memory")

#define MMA_TF32(d, av, bv)                                               \
    asm volatile(                                                         \
        "mma.sync.aligned.m16n8k8.row.col.f32.tf32.tf32.f32 "             \
        "{%0,%1,%2,%3},{%4,%5,%6,%7},{%8,%9},{%0,%1,%2,%3};"              \
        : "+f"((d)[0]), "+f"((d)[1]), "+f"((d)[2]), "+f"((d)[3])          \
        : "r"((av)[0]), "r"((av)[1]), "r"((av)[2]), "r"((av)[3]),         \
          "r"((bv)[0]), "r"((bv)[1]))

// ---------------- CSR build ----------------
__global__ void k_count(const int* __restrict__ dst) {
    int e = blockIdx.x * blockDim.x + threadIdx.x;
    if (e < Ee) atomicAdd(&g_deg[dst[e]], 1);
}
__global__ void k_scan1() {
    __shared__ int s[1024];
    int i = blockIdx.x * 1024 + threadIdx.x;
    int v = (i < Nn) ? g_deg[i] : 0;
    s[threadIdx.x] = v;
    __syncthreads();
    for (int off = 1; off < 1024; off <<= 1) {
        int t = (threadIdx.x >= off) ? s[threadIdx.x - off] : 0;
        __syncthreads();
        s[threadIdx.x] += t;
        __syncthreads();
    }
    if (i < Nn) g_scan[i] = s[threadIdx.x];
    if (threadIdx.x == 1023) g_bsum[blockIdx.x] = s[1023];
}
__global__ void k_scan2(int nb) {
    __shared__ int s[128];
    int v = (threadIdx.x < nb) ? g_bsum[threadIdx.x] : 0;
    s[threadIdx.x] = v;
    __syncthreads();
    for (int off = 1; off < 128; off <<= 1) {
        int t = (threadIdx.x >= off) ? s[threadIdx.x - off] : 0;
        __syncthreads();
        s[threadIdx.x] += t;
        __syncthreads();
    }
    g_bsum[threadIdx.x] = (threadIdx.x == 0) ? 0 : s[threadIdx.x - 1];
}
__global__ void k_finalize() {
    int i = blockIdx.x * blockDim.x + threadIdx.x;
    if (i >= Nn) return;
    int incl = g_scan[i] + g_bsum[i >> 10];
    g_rowptr[i + 1] = incl;
    g_cursor[i] = incl - g_deg[i];
    if (i == 0) g_rowptr[0] = 0;
}
__global__ void k_fill(const int* __restrict__ dst, const int* __restrict__ src) {
    int e = blockIdx.x * blockDim.x + threadIdx.x;
    if (e < Ee) {
        int d = dst[e];
        int p = atomicAdd(&g_cursor[d], 1);
        g_srcs[p] = src[e];
    }
}

// ---------------- all-weight cvt ----------------
__global__ void k_cvt_all(const float* __restrict__ gat_W, const float* __restrict__ ff_W1,
                          const float* __restrict__ ff_W2, const float* __restrict__ dec_W1,
                          const float* __restrict__ emb_W2) {
    int i = blockIdx.x * blockDim.x + threadIdx.x;
    if (i >= 425984) return;
    float v;
    if (i < 65536) v = gat_W[i];
    else if (i < 196608) v = ff_W1[i - 65536];
    else if (i < 327680) v = ff_W2[i - 196608];
    else if (i < 409600) v = dec_W1[i - 327680];
    else v = emb_W2[i - 409600];
    g_W[i] = to_tf32(v);
}

// ---------------- embed stage 1 ----------------
__global__ void k_embed1(const float* __restrict__ x,
                         const float* __restrict__ W1, const float* __restrict__ b1,
                         const float* __restrict__ b2,
                         const float* __restrict__ Ws, const float* __restrict__ bs) {
    int idx = blockIdx.x * blockDim.x + threadIdx.x;
    if (idx >= Nn * 128) return;
    int n = idx >> 7, c = idx & 127;
    float x0 = x[n * 2], x1 = x[n * 2 + 1];
    float tv = fmaf(x0, W1[c], fmaf(x1, W1[128 + c], b1[c]));
    g_t[idx] = tv > 0.f ? tv : 0.f;
    g_y[idx] = fmaf(x0, Ws[c], fmaf(x1, Ws[128 + c], bs[c] + b2[c]));
}

// ---------------- generic fused tf32 tensor GEMM (512 thr) ----------------
template <int RELU, int BIAS, int RES, int BN, int ELER, int AAFF, int RAFF, int DEC>
__global__ void __launch_bounds__(512, 2) k_tgemm(
    const float* __restrict__ A, int lda,
    const float* __restrict__ B,
    const float* __restrict__ bias,
    const float* __restrict__ Res, int ldres,
    float* __restrict__ C, int ldc,
    int Nrows, int Mred, int Kcols, float* bnslot,
    const float* affA, const float* affAg, const float* affAb,
    const float* affR, const float* affRg, const float* affRb,
    const float* al, const float* ar) {
    constexpr int S = 4;
    constexpr int ASTG = 128 * 20;
    constexpr int BSTG = 16 * 136;
    constexpr int STGF = S * ASTG + S * BSTG;
    constexpr int SCA = STGF, SHA = SCA + 640, SCR = SHA + 640, SHR = SCR + 128;
    constexpr int ALO = SHR + 128, ARO = ALO + 128;
    extern __shared__ float sm[];
    float* AsF = sm;
    float* BsF = sm + S * ASTG;

    const int tid = threadIdx.x;
    const int lane = tid & 31;
    const int wid = tid >> 5;
    const int bm = blockIdx.x * 128;
    const int bn = blockIdx.y * 128;

    const int m0 = (wid & 3) * 32;
    const int n0 = (wid >> 2) * 32;
    const int qrow = lane >> 2;
    const int qk = lane & 3;

    const int arow = tid >> 2;
    const int aseg = (tid & 3) * 4;
    const int brow = tid >> 5;
    const int bcol = (tid & 31) * 4;

    const int gr = bm + arow;
    const bool aok = gr < Nrows;
    const float* Asrc = A + (size_t)gr * lda + aseg;
    const float* Bsrc = B + (size_t)brow * Kcols + bn + bcol;
    const uint32_t adst = smem_to_u32(AsF) + (uint32_t)(arow * 20 + aseg) * 4u;
    const uint32_t bdst = smem_to_u32(BsF) + (uint32_t)(brow * 136 + bcol) * 4u;

    const int nIter = Mred >> 4;

#pragma unroll
    for (int s = 0; s < S - 1; s++) {
        if (s < nIter) {
            int kt = s << 4;
            cp16(adst + (uint32_t)(s * ASTG) * 4u, Asrc + kt, aok);
            cp16(bdst + (uint32_t)(s * BSTG) * 4u, Bsrc + (size_t)kt * Kcols, true);
        }
        CP_COMMIT();
    }

    const float invN = 1.f / (float)Nn;
    if (AAFF) {
        for (int k = tid; k < Mred; k += 512) {
            float scv = 1.f, shv = 0.f;
            const float *slot = nullptr, *gg = nullptr, *bb = nullptr;
            int c = k;
            if (AAFF == 1) { slot = affA; gg = affAg; bb = affAb; }
            else {
                int blk = k >> 7;
                c = k & 127;
                if (blk > 0) {
                    slot = g_bnsum + (size_t)(2 * (blk - 1) + 1) * 256;
                    gg = affAg + (blk - 1) * 128;
                    bb = affAb + (blk - 1) * 128;
                }
            }
            if (slot) {
                float mu = slot[c] * invN;
                float var = slot[c + 128] * invN - mu * mu;
                float rs = rsqrtf(var + EPSBN);
                scv = gg[c] * rs;
                shv = bb[c] - mu * scv;
            }
            sm[SCA + k] = scv;
            sm[SHA + k] = shv;
        }
    }
    if (RAFF) {
        if (tid < 128) {
            float mu = affR[tid] * invN;
            float var = affR[tid + 128] * invN - mu * mu;
            float rs = rsqrtf(var + EPSBN);
            float scv = affRg[tid] * rs;
            sm[SCR + tid] = scv;
            sm[SHR + tid] = affRb[tid] - mu * scv;
        }
    }
    if (ELER) {
        if (tid < 128) sm[ALO + tid] = al[tid];
        else if (tid < 256) sm[ARO + tid - 128] = ar[tid - 128];
    }
    if (DEC) {
        if (tid < 128) sm[ALO + tid] = al[tid];
    }

    float acc[2][4][4];
#pragma unroll
    for (int mi = 0; mi < 2; mi++)
#pragma unroll
        for (int ni = 0; ni < 4; ni++)
#pragma unroll
            for (int j = 0; j < 4; j++) acc[mi][ni][j] = 0.f;

    for (int it = 0; it < nIter; it++) {
        CP_WAIT2();
        __syncthreads();

        const int stg = it & (S - 1);
        const float* as = AsF + stg * ASTG;
        const float* bs = BsF + stg * BSTG;
#pragma unroll
        for (int ks = 0; ks < 2; ks++) {
            const int kbase = ks * 8;
            float sc0 = 1.f, sc1 = 1.f, sh0 = 0.f, sh1 = 0.f;
            if (AAFF) {
                int kg = (it << 4) + kbase + qk;
                sc0 = sm[SCA + kg]; sh0 = sm[SHA + kg];
                sc1 = sm[SCA + kg + 4]; sh1 = sm[SHA + kg + 4];
            }
            uint32_t a[2][4];
#pragma unroll
            for (int mi = 0; mi < 2; mi++) {
                const float* ap = as + (m0 + mi * 16 + qrow) * 20 + kbase + qk;
                if (AAFF) {
                    a[mi][0] = __float_as_uint(to_tf32(fmaf(ap[0], sc0, sh0)));
                    a[mi][1] = __float_as_uint(to_tf32(fmaf(ap[8 * 20], sc0, sh0)));
                    a[mi][2] = __float_as_uint(to_tf32(fmaf(ap[4], sc1, sh1)));
                    a[mi][3] = __float_as_uint(to_tf32(fmaf(ap[8 * 20 + 4], sc1, sh1)));
                } else {
                    a[mi][0] = __float_as_uint(to_tf32(ap[0]));
                    a[mi][1] = __float_as_uint(to_tf32(ap[8 * 20]));
                    a[mi][2] = __float_as_uint(to_tf32(ap[4]));
                    a[mi][3] = __float_as_uint(to_tf32(ap[8 * 20 + 4]));
                }
            }
            uint32_t b[4][2];
#pragma unroll
            for (int ni = 0; ni < 4; ni++) {
                const float* bp = bs + (kbase + qk) * 136 + n0 + ni * 8 + qrow;
                b[ni][0] = __float_as_uint(bp[0]);
                b[ni][1] = __float_as_uint(bp[4 * 136]);
            }
#pragma unroll
            for (int mi = 0; mi < 2; mi++)
#pragma unroll
                for (int ni = 0; ni < 4; ni++) MMA_TF32(acc[mi][ni], a[mi], b[ni]);
        }

        const int nx = it + S - 1;
        if (nx < nIter) {
            const int s = nx & (S - 1);
            const int kt = nx << 4;
            cp16(adst + (uint32_t)(s * ASTG) * 4u, Asrc + kt, aok);
            cp16(bdst + (uint32_t)(s * BSTG) * 4u, Bsrc + (size_t)kt * Kcols, true);
        }
        CP_COMMIT();
    }

    // epilogue
    float s0[4], s1[4], q0[4], q1[4];
    if (BN) {
#pragma unroll
        for (int ni = 0; ni < 4; ni++) { s0[ni] = 0.f; s1[ni] = 0.f; q0[ni] = 0.f; q1[ni] = 0.f; }
    }
#pragma unroll
    for (int mi = 0; mi < 2; mi++) {
#pragma unroll
        for (int half = 0; half < 2; half++) {
            int r = bm + m0 + mi * 16 + qrow + half * 8;
            bool rok = r < Nrows;
            float pd = 0.f;
#pragma unroll
            for (int ni = 0; ni < 4; ni++) {
                int gcl = n0 + ni * 8 + qk * 2;
                int gc = bn + gcl;
                float v0 = acc[mi][ni][half * 2 + 0];
                float v1 = acc[mi][ni][half * 2 + 1];
                if (BIAS) {
                    v0 += bias[gc];
                    v1 += bias[gc + 1];
                }
                if (RELU) {
                    v0 = fmaxf(v0, 0.f);
                    v1 = fmaxf(v1, 0.f);
                }
                if (RES && rok) {
                    const float* rp = Res + (size_t)r * ldres + gc;
                    float rv0 = rp[0], rv1 = rp[1];
                    if (RAFF) {
                        rv0 = fmaf(rv0, sm[SCR + gc], sm[SHR + gc]);
                        rv1 = fmaf(rv1, sm[SCR + gc + 1], sm[SHR + gc + 1]);
                    }
                    v0 += rv0;
                    v1 += rv1;
                }
                if (!DEC && rok) *(float2*)(C + (size_t)r * ldc + gc) = make_float2(v0, v1);
                if (BN && rok) {
                    s0[ni] += v0; q0[ni] += v0 * v0;
                    s1[ni] += v1; q1[ni] += v1 * v1;
                }
                if (DEC) pd = fmaf(v0, sm[ALO + gcl], fmaf(v1, sm[ALO + gcl + 1], pd));
                if (ELER) {
                    int h = (n0 >> 3) + ni;
                    float p = fmaf(v0, sm[ALO + h * 8 + qk * 2], v1 * sm[ALO + h * 8 + qk * 2 + 1]);
                    float q = fmaf(v0, sm[ARO + h * 8 + qk * 2], v1 * sm[ARO + h * 8 + qk * 2 + 1]);
                    p += __shfl_xor_sync(0xffffffffu, p, 1);
                    p += __shfl_xor_sync(0xffffffffu, p, 2);
                    q += __shfl_xor_sync(0xffffffffu, q, 1);
                    q += __shfl_xor_sync(0xffffffffu, q, 2);
                    if ((lane & 3) == 0 && rok) {
                        g_el[r * 16 + h] = p;
                        g_er[r * 16 + h] = q;
                    }
                }
            }
            if (DEC) {
                pd += __shfl_xor_sync(0xffffffffu, pd, 1);
                pd += __shfl_xor_sync(0xffffffffu, pd, 2);
                if ((lane & 3) == 0 && rok)
                    atomicAdd(C + r, pd + 0.25f * ar[0]);
            }
        }
    }

    if (BN) {
#pragma unroll
        for (int ni = 0; ni < 4; ni++) {
            s0[ni] += __shfl_xor_sync(0xffffffffu, s0[ni], 4);
            s0[ni] += __shfl_xor_sync(0xffffffffu, s0[ni], 8);
            s0[ni] += __shfl_xor_sync(0xffffffffu, s0[ni], 16);
            s1[ni] += __shfl_xor_sync(0xffffffffu, s1[ni], 4);
            s1[ni] += __shfl_xor_sync(0xffffffffu, s1[ni], 8);
            s1[ni] += __shfl_xor_sync(0xffffffffu, s1[ni], 16);
            q0[ni] += __shfl_xor_sync(0xffffffffu, q0[ni], 4);
            q0[ni] += __shfl_xor_sync(0xffffffffu, q0[ni], 8);
            q0[ni] += __shfl_xor_sync(0xffffffffu, q0[ni], 16);
            q1[ni] += __shfl_xor_sync(0xffffffffu, q1[ni], 4);
            q1[ni] += __shfl_xor_sync(0xffffffffu, q1[ni], 8);
            q1[ni] += __shfl_xor_sync(0xffffffffu, q1[ni], 16);
        }
        __syncthreads();
        if (lane < 4) {
            int mg = wid & 3;
#pragma unroll
            for (int ni = 0; ni < 4; ni++) {
                int c = n0 + ni * 8 + lane * 2;
                sm[mg * 128 + c] = s0[ni];
                sm[mg * 128 + c + 1] = s1[ni];
                sm[512 + mg * 128 + c] = q0[ni];
                sm[512 + mg * 128 + c + 1] = q1[ni];
            }
        }
        __syncthreads();
        if (tid < 256) {
            int c = tid & 127, st = tid >> 7;
            float v = sm[st * 512 + c] + sm[st * 512 + 128 + c] +
                      sm[st * 512 + 256 + c] + sm[st * 512 + 384 + c];
            atomicAdd(bnslot + st * 128 + c, v);
        }
    }
}

// ---------------- fused FF kernel: HC_next = T@W2 + b2 + BN1(y), T = relu(BN1(y)@W1 + b1) ----------------
// smem floats: Y[128][132]=16896 | T[128][260]=33280 | W 4352 | SCA 128 | SHA 128 | SB1 256
__global__ void __launch_bounds__(512, 1) k_ff(
    const float* __restrict__ y,
    const float* __restrict__ W1, const float* __restrict__ b1v,
    const float* __restrict__ W2, const float* __restrict__ b2v,
    float* __restrict__ C, int ldc,
    const float* __restrict__ slot1, const float* __restrict__ g1, const float* __restrict__ bb1,
    float* __restrict__ bnslot) {
    constexpr int YOFF = 0;
    constexpr int TOFF = 16896;
    constexpr int WOFF = TOFF + 33280;   // 50176
    constexpr int SCA = WOFF + 4352;     // 54528
    constexpr int SHA = SCA + 128;
    constexpr int SB1 = SHA + 128;       // ..55040
    extern __shared__ float sm[];
    const int tid = threadIdx.x, lane = tid & 31, wid = tid >> 5;
    const int bm = blockIdx.x * 128;
    const int qrow = lane >> 2, qk = lane & 3;
    const uint32_t smb = smem_to_u32(sm);

    // load full Y tile (128x128)
    {
        int row = tid >> 2, cb = (tid & 3) * 32;
        bool ok = (bm + row) < Nn;
        const float* srcp = y + (size_t)(bm + row) * 128 + cb;
        uint32_t dst = smb + (uint32_t)(YOFF + row * 132 + cb) * 4u;
#pragma unroll
        for (int j = 0; j < 8; j++) cp16(dst + j * 16u, srcp + j * 4, ok);
    }
    // W1 chunk 0 (rows 0..7 of [128][256])
    {
        int r = tid >> 6, c = (tid & 63) * 4;
        cp16(smb + (uint32_t)(WOFF + r * 264 + c) * 4u, W1 + r * 256 + c, true);
    }
    CP_COMMIT();
    const float invN = 1.f / (float)Nn;
    if (tid < 128) {
        float mu = slot1[tid] * invN;
        float var = slot1[tid + 128] * invN - mu * mu;
        float sc = g1[tid] * rsqrtf(var + EPSBN);
        sm[SCA + tid] = sc;
        sm[SHA + tid] = bb1[tid] - mu * sc;
    } else if (tid < 384) {
        sm[SB1 + tid - 128] = b1v[tid - 128];
    }
    CP_WAIT0();
    __syncthreads();

    // ---- stage A: T = relu(BN1(Y) @ W1 + b1), reduction over 128 Y cols (16 chunks x 8) ----
    const int m0A = (wid & 3) * 32, n0A = (wid >> 2) * 64;
    float accA[2][8][4];
#pragma unroll
    for (int mi = 0; mi < 2; mi++)
#pragma unroll
        for (int ni = 0; ni < 8; ni++)
#pragma unroll
            for (int j = 0; j < 4; j++) accA[mi][ni][j] = 0.f;

    for (int it = 0; it < 16; it++) {
        if (it + 1 < 16) {
            int r = tid >> 6, c = (tid & 63) * 4;
            cp16(smb + (uint32_t)(WOFF + ((it + 1) & 1) * 2112 + r * 264 + c) * 4u,
                 W1 + (size_t)((it + 1) * 8 + r) * 256 + c, true);
        }
        CP_COMMIT();
        CP_WAIT1();
        __syncthreads();
        const float* bs = sm + WOFF + (it & 1) * 2112;
        int kg = it * 8 + qk;
        float sc0 = sm[SCA + kg], sh0 = sm[SHA + kg];
        float sc1 = sm[SCA + kg + 4], sh1 = sm[SHA + kg + 4];
        uint32_t a[2][4];
#pragma unroll
        for (int mi = 0; mi < 2; mi++) {
            const float* ap = sm + YOFF + (m0A + mi * 16 + qrow) * 132 + it * 8 + qk;
            a[mi][0] = __float_as_uint(to_tf32(fmaf(ap[0], sc0, sh0)));
            a[mi][1] = __float_as_uint(to_tf32(fmaf(ap[8 * 132], sc0, sh0)));
            a[mi][2] = __float_as_uint(to_tf32(fmaf(ap[4], sc1, sh1)));
            a[mi][3] = __float_as_uint(to_tf32(fmaf(ap[8 * 132 + 4], sc1, sh1)));
        }
#pragma unroll
        for (int ni = 0; ni < 8; ni++) {
            uint32_t b[2];
            const float* bp = bs + qk * 264 + n0A + ni * 8 + qrow;
            b[0] = __float_as_uint(bp[0]);
            b[1] = __float_as_uint(bp[4 * 264]);
#pragma unroll
            for (int mi = 0; mi < 2; mi++) MMA_TF32(accA[mi][ni], a[mi], b);
        }
        __syncthreads();
    }

    // write T = relu(acc + b1)
#pragma unroll
    for (int mi = 0; mi < 2; mi++) {
#pragma unroll
        for (int half = 0; half < 2; half++) {
            int rl = m0A + mi * 16 + half * 8 + qrow;
#pragma unroll
            for (int ni = 0; ni < 8; ni++) {
                int c = n0A + ni * 8 + qk * 2;
                float v0 = fmaxf(accA[mi][ni][half * 2 + 0] + sm[SB1 + c], 0.f);
                float v1 = fmaxf(accA[mi][ni][half * 2 + 1] + sm[SB1 + c + 1], 0.f);
                *(float2*)&sm[TOFF + rl * 260 + c] = make_float2(v0, v1);
            }
        }
    }
    __syncthreads();

    // ---- stage B: HC = T @ W2 + b2 + BN1(Y), reduction over 256 T cols (16 chunks x 16) ----
    const int m0B = (wid & 3) * 32, n0B = (wid >> 2) * 32;
    float accB[2][4][4];
#pragma unroll
    for (int mi = 0; mi < 2; mi++)
#pragma unroll
        for (int ni = 0; ni < 4; ni++)
#pragma unroll
            for (int j = 0; j < 4; j++) accB[mi][ni][j] = 0.f;

    {
        int r = tid >> 5, c = (tid & 31) * 4;
        cp16(smb + (uint32_t)(WOFF + r * 136 + c) * 4u, W2 + r * 128 + c, true);
    }
    CP_COMMIT();

    for (int it = 0; it < 16; it++) {  // FIXED: 16 chunks (256 k), was 8
        if (it + 1 < 16) {
            int r = tid >> 5, c = (tid & 31) * 4;
            cp16(smb + (uint32_t)(WOFF + ((it + 1) & 1) * 2176 + r * 136 + c) * 4u,
                 W2 + (size_t)((it + 1) * 16 + r) * 128 + c, true);
        }
        CP_COMMIT();
        CP_WAIT1();
        __syncthreads();
        const float* bs = sm + WOFF + (it & 1) * 2176;
#pragma unroll
        for (int ks = 0; ks < 2; ks++) {
            int kb = it * 16 + ks * 8;
            uint32_t a[2][4];
#pragma unroll
            for (int mi = 0; mi < 2; mi++) {
                const float* ap = sm + TOFF + (m0B + mi * 16 + qrow) * 260 + kb + qk;
                a[mi][0] = __float_as_uint(to_tf32(ap[0]));
                a[mi][1] = __float_as_uint(to_tf32(ap[8 * 260]));
                a[mi][2] = __float_as_uint(to_tf32(ap[4]));
                a[mi][3] = __float_as_uint(to_tf32(ap[8 * 260 + 4]));
            }
#pragma unroll
            for (int ni = 0; ni < 4; ni++) {
                uint32_t b[2];
                const float* bp = bs + (ks * 8 + qk) * 136 + n0B + ni * 8 + qrow;
                b[0] = __float_as_uint(bp[0]);
                b[1] = __float_as_uint(bp[4 * 136]);
#pragma unroll
                for (int mi = 0; mi < 2; mi++) MMA_TF32(accB[mi][ni], a[mi], b);
            }
        }
        __syncthreads();
    }

    // epilogue: + b2 + BN1(y) residual, write HC, BN2 stats
    float s0[4], s1[4], q0[4], q1[4];
#pragma unroll
    for (int ni = 0; ni < 4; ni++) { s0[ni] = 0.f; s1[ni] = 0.f; q0[ni] = 0.f; q1[ni] = 0.f; }
#pragma unroll
    for (int mi = 0; mi < 2; mi++) {
#pragma unroll
        for (int half = 0; half < 2; half++) {
            int rl = m0B + mi * 16 + half * 8 + qrow;
            int r = bm + rl;
            bool rok = r < Nn;
#pragma unroll
            for (int ni = 0; ni < 4; ni++) {
                int gc = n0B + ni * 8 + qk * 2;
                float yv0 = fmaf(sm[YOFF + rl * 132 + gc], sm[SCA + gc], sm[SHA + gc]);
                float yv1 = fmaf(sm[YOFF + rl * 132 + gc + 1], sm[SCA + gc + 1], sm[SHA + gc + 1]);
                float v0 = accB[mi][ni][half * 2 + 0] + b2v[gc] + yv0;
                float v1 = accB[mi][ni][half * 2 + 1] + b2v[gc + 1] + yv1;
                if (rok) {
                    *(float2*)(C + (size_t)r * ldc + gc) = make_float2(v0, v1);
                    s0[ni] += v0; q0[ni] += v0 * v0;
                    s1[ni] += v1; q1[ni] += v1 * v1;
                }
            }
        }
    }
#pragma unroll
    for (int ni = 0; ni < 4; ni++) {
        s0[ni] += __shfl_xor_sync(0xffffffffu, s0[ni], 4);
        s0[ni] += __shfl_xor_sync(0xffffffffu, s0[ni], 8);
        s0[ni] += __shfl_xor_sync(0xffffffffu, s0[ni], 16);
        s1[ni] += __shfl_xor_sync(0xffffffffu, s1[ni], 4);
        s1[ni] += __shfl_xor_sync(0xffffffffu, s1[ni], 8);
        s1[ni] += __shfl_xor_sync(0xffffffffu, s1[ni], 16);
        q0[ni] += __shfl_xor_sync(0xffffffffu, q0[ni], 4);
        q0[ni] += __shfl_xor_sync(0xffffffffu, q0[ni], 8);
        q0[ni] += __shfl_xor_sync(0xffffffffu, q0[ni], 16);
        q1[ni] += __shfl_xor_sync(0xffffffffu, q1[ni], 4);
        q1[ni] += __shfl_xor_sync(0xffffffffu, q1[ni], 8);
        q1[ni] += __shfl_xor_sync(0xffffffffu, q1[ni], 16);
    }
    __syncthreads();
    if (lane < 4) {
        int mg = wid & 3;
#pragma unroll
        for (int ni = 0; ni < 4; ni++) {
            int c = n0B + ni * 8 + lane * 2;
            sm[mg * 128 + c] = s0[ni];
            sm[mg * 128 + c + 1] = s1[ni];
            sm[512 + mg * 128 + c] = q0[ni];
            sm[512 + mg * 128 + c + 1] = q1[ni];
        }
    }
    __syncthreads();
    if (tid < 256) {
        int c = tid & 127, st = tid >> 7;
        float v = sm[st * 512 + c] + sm[st * 512 + 128 + c] +
                  sm[st * 512 + 256 + c] + sm[st * 512 + 384 + c];
        atomicAdd(bnslot + st * 128 + c, v);
    }
}

// ---------------- GAT aggregate: single-pass softmax + prefetch + fused BN1 stats ----------------
__global__ void k_gat(const float* __restrict__ z,
                      const float* __restrict__ hres, int ldh,
                      const float* __restrict__ bias, float* __restrict__ y,
                      float* __restrict__ bnslot,
                      const float* __restrict__ slotPrev,
                      const float* __restrict__ gPrev, const float* __restrict__ bPrev) {
    __shared__ float sbn[2][8][128];
    int gw = (blockIdx.x * blockDim.x + threadIdx.x) >> 5;
    int lane = threadIdx.x & 31;
    int wid = threadIdx.x >> 5;
    float4 o = make_float4(0.f, 0.f, 0.f, 0.f);
    if (gw < Nn) {
        int head = lane >> 1;
        int beg = g_rowptr[gw], end = g_rowptr[gw + 1];
        float er_h = g_er[gw * 16 + head];
        const float4* z4 = (const float4*)z;

        float den = 0.f;
        float4 acc = make_float4(0.f, 0.f, 0.f, 0.f);
        float eN = 0.f;
        float4 zN = make_float4(0.f, 0.f, 0.f, 0.f);
        if (beg < end) {
            int s0i = g_srcs[beg];
            eN = g_el[s0i * 16 + head];
            zN = z4[(size_t)s0i * 32 + lane];
        }
        for (int i = beg; i < end; i++) {
            float e = eN + er_h;
            float4 zc = zN;
            if (i + 1 < end) {
                int s = g_srcs[i + 1];
                eN = g_el[s * 16 + head];
                zN = z4[(size_t)s * 32 + lane];
            }
            e = e > 0.f ? e : SLOPE * e;
            float w = __expf(e);
            den += w;
            acc.x += w * zc.x; acc.y += w * zc.y; acc.z += w * zc.z; acc.w += w * zc.w;
        }
        float dinv = den > 0.f ? 1.f / den : 1.f;
        float4 b4 = ((const float4*)bias)[lane];
        float4 h4 = *(const float4*)(hres + (size_t)gw * ldh + lane * 4);
        if (slotPrev != nullptr) {
            const float invN = 1.f / (float)Nn;
            int c = lane * 4;
#pragma unroll
            for (int j = 0; j < 4; j++) {
                float mu = slotPrev[c + j] * invN;
                float var = slotPrev[128 + c + j] * invN - mu * mu;
                float sc = gPrev[c + j] * rsqrtf(var + EPSBN);
                float sh = bPrev[c + j] - mu * sc;
                float* hp = (&h4.x) + j;
                *hp = fmaf(*hp, sc, sh);
            }
        }
        o.x = acc.x * dinv + b4.x + h4.x;
        o.y = acc.y * dinv + b4.y + h4.y;
        o.z = acc.z * dinv + b4.z + h4.z;
        o.w = acc.w * dinv + b4.w + h4.w;
        ((float4*)y)[(size_t)gw * 32 + lane] = o;
    }
    ((float4*)sbn[0][wid])[lane] = o;
    ((float4*)sbn[1][wid])[lane] = make_float4(o.x * o.x, o.y * o.y, o.z * o.z, o.w * o.w);
    __syncthreads();
    int c = threadIdx.x & 127, st = threadIdx.x >> 7;
    float v = 0.f;
#pragma unroll
    for (int w = 0; w < 8; w++) v += sbn[st][w][c];
    atomicAdd(bnslot + st * 128 + c, v);
}

// ---------------- launch ----------------
extern "C" void kernel_launch(void* const* d_in, const int* in_sizes, int n_in,
                              void* d_out, int out_size) {
    const float* x      = (const float*)d_in[0];
    const int*   src    = (const int*)d_in[1];
    const int*   dst    = (const int*)d_in[2];
    const float* emb_W1 = (const float*)d_in[3];
    const float* emb_b1 = (const float*)d_in[4];
    const float* emb_W2 = (const float*)d_in[5];
    const float* emb_b2 = (const float*)d_in[6];
    const float* emb_Ws = (const float*)d_in[7];
    const float* emb_bs = (const float*)d_in[8];
    const float* gat_W  = (const float*)d_in[9];
    const float* gat_al = (const float*)d_in[10];
    const float* gat_ar = (const float*)d_in[11];
    const float* gat_b  = (const float*)d_in[12];
    const float* bn1_g  = (const float*)d_in[13];
    const float* bn1_b  = (const float*)d_in[14];
    const float* ff_W1  = (const float*)d_in[15];
    const float* ff_b1  = (const float*)d_in[16];
    const float* ff_W2  = (const float*)d_in[17];
    const float* ff_b2  = (const float*)d_in[18];
    const float* bn2_g  = (const float*)d_in[19];
    const float* bn2_b  = (const float*)d_in[20];
    const float* dec_W1 = (const float*)d_in[21];
    const float* dec_b1 = (const float*)d_in[22];
    const float* dec_W2 = (const float*)d_in[23];
    const float* dec_b2 = (const float*)d_in[24];

    void* p;
    float *HC, *zb, *tb, *yb, *bns, *W;
    int* degp;
    cudaGetSymbolAddress(&p, g_HC);    HC = (float*)p;
    cudaGetSymbolAddress(&p, g_z);     zb = (float*)p;
    cudaGetSymbolAddress(&p, g_t);     tb = (float*)p;
    cudaGetSymbolAddress(&p, g_y);     yb = (float*)p;
    cudaGetSymbolAddress(&p, g_bnsum); bns = (float*)p;
    cudaGetSymbolAddress(&p, g_deg);   degp = (int*)p;
    cudaGetSymbolAddress(&p, g_W);     W = (float*)p;

    float* Wg = W;
    float* Wf1 = W + 65536;
    float* Wf2 = W + 196608;
    float* Wd = W + 327680;
    float* We2 = W + 409600;

    const int SMEM = 20736 * 4;        // 82944 B (generic)
    const int SMEM_FF = 55040 * 4;     // 220160 B (fused FF)
    static bool attrDone = false;
    if (!attrDone) {
        cudaFuncSetAttribute(k_tgemm<0, 0, 1, 0, 0, 0, 0, 0>, cudaFuncAttributeMaxDynamicSharedMemorySize, SMEM);
        cudaFuncSetAttribute(k_tgemm<0, 0, 0, 0, 1, 0, 0, 0>, cudaFuncAttributeMaxDynamicSharedMemorySize, SMEM);
        cudaFuncSetAttribute(k_tgemm<0, 0, 0, 0, 1, 1, 0, 0>, cudaFuncAttributeMaxDynamicSharedMemorySize, SMEM);
        cudaFuncSetAttribute(k_tgemm<1, 1, 0, 0, 0, 2, 0, 1>, cudaFuncAttributeMaxDynamicSharedMemorySize, SMEM);
        cudaFuncSetAttribute(k_ff, cudaFuncAttributeMaxDynamicSharedMemorySize, SMEM_FF);
        attrDone = true;
    }

    cudaMemsetAsync(bns, 0, 8 * 256 * sizeof(float));
    cudaMemsetAsync(degp, 0, Nn * sizeof(int));
    cudaMemsetAsync(d_out, 0, (size_t)out_size * sizeof(float));

    k_cvt_all<<<(425984 + 255) / 256, 256>>>(gat_W, ff_W1, ff_W2, dec_W1, emb_W2);
    k_embed1<<<(Nn * 128 + 255) / 256, 256>>>(x, emb_W1, emb_b1, emb_b2, emb_Ws, emb_bs);
    k_count<<<(Ee + 255) / 256, 256>>>(dst);

    const int gx = (Nn + 127) / 128;  // 782
    dim3 grid1(gx, 1);
    const int warpBlocks = (Nn * 32 + 255) / 256;

    // embed stage 2 GEMM
    k_tgemm<0, 0, 1, 0, 0, 0, 0, 0><<<grid1, 512, SMEM>>>(
        tb, 128, We2, nullptr, yb, 128, HC, 640, Nn, 128, 128, nullptr,
        nullptr, nullptr, nullptr, nullptr, nullptr, nullptr, nullptr, nullptr);

    const int nb = (Nn + 1023) / 1024;
    k_scan1<<<nb, 1024>>>();
    k_scan2<<<1, 128>>>(nb);
    k_finalize<<<(Nn + 255) / 256, 256>>>();
    k_fill<<<(Ee + 255) / 256, 256>>>(dst, src);

    for (int l = 0; l < 4; l++) {
        const float* h = HC + l * 128;
        float* slot1 = bns + (size_t)(2 * l) * 256;
        float* slot2 = bns + (size_t)(2 * l + 1) * 256;
        const float* slotP = (l > 0) ? (bns + (size_t)(2 * (l - 1) + 1) * 256) : nullptr;
        const float* gP = (l > 0) ? (bn2_g + (l - 1) * 128) : nullptr;
        const float* bP = (l > 0) ? (bn2_b + (l - 1) * 128) : nullptr;

        if (l == 0) {
            k_tgemm<0, 0, 0, 0, 1, 0, 0, 0><<<grid1, 512, SMEM>>>(
                h, 640, Wg, nullptr, nullptr, 0, zb, 128, Nn, 128, 128, nullptr,
                nullptr, nullptr, nullptr, nullptr, nullptr, nullptr,
                gat_al, gat_ar);
        } else {
            k_tgemm<0, 0, 0, 0, 1, 1, 0, 0><<<grid1, 512, SMEM>>>(
                h, 640, Wg + (size_t)l * 16384, nullptr, nullptr, 0, zb, 128, Nn, 128, 128, nullptr,
                slotP, gP, bP, nullptr, nullptr, nullptr,
                gat_al + l * 128, gat_ar + l * 128);
        }
        k_gat<<<warpBlocks, 256>>>(zb, h, 640, gat_b + l * 128, yb, slot1, slotP, gP, bP);
        // fused FF pair -> HC block l+1 (raw), BN2 stats fused
        k_ff<<<grid1, 512, SMEM_FF>>>(
            yb, Wf1 + (size_t)l * 32768, ff_b1 + l * 256,
            Wf2 + (size_t)l * 32768, ff_b2 + l * 128,
            HC + (size_t)(l + 1) * 128, 640,
            slot1, bn1_g + l * 128, bn1_b + l * 128, slot2);
    }

    // decoder: relu(affine_concat(HC) @ Wd + b1) . W2 + b2 (fused dot, atomic partials)
    k_tgemm<1, 1, 0, 0, 0, 2, 0, 1><<<grid1, 512, SMEM>>>(
        HC, 640, Wd, dec_b1, nullptr, 0, (float*)d_out, 1, Nn, 640, 128, nullptr,
        nullptr, bn2_g, bn2_b, nullptr, nullptr, nullptr, dec_W2, dec_b2);
}